// round 1
// baseline (speedup 1.0000x reference)
#include <cuda_runtime.h>
#include <math.h>

#define DIM   1024
#define HEADS 16
#define HDIM  64
#define MLP   4096
#define BB    4
#define SS    2048
#define TT    (BB*SS)   // 8192 tokens

// ---------------- scratch (device globals; no allocation) ----------------
__device__ float g_xn[(size_t)TT*DIM];     // LN output (reused)
__device__ float g_qkv[(size_t)TT*3*DIM];  // qkv projections
__device__ float g_attn[(size_t)TT*DIM];   // attention output (pre-proj)
__device__ float g_x1[(size_t)TT*DIM];     // residual after attention
__device__ float g_h[(size_t)TT*MLP];      // MLP hidden

// ---------------- LayerNorm: one block (256 threads) per row ----------------
__global__ __launch_bounds__(256)
void ln_kernel(const float* __restrict__ x, const float* __restrict__ w,
               const float* __restrict__ b, float* __restrict__ out) {
    int row = blockIdx.x;
    int tid = threadIdx.x;
    const float4* xr = (const float4*)(x + (size_t)row * DIM);
    float4 v = xr[tid];  // 256 * 4 = 1024
    float s  = v.x + v.y + v.z + v.w;
    float ss = v.x*v.x + v.y*v.y + v.z*v.z + v.w*v.w;
    #pragma unroll
    for (int o = 16; o; o >>= 1) {
        s  += __shfl_xor_sync(0xffffffffu, s,  o);
        ss += __shfl_xor_sync(0xffffffffu, ss, o);
    }
    __shared__ float red0[8], red1[8];
    int wid = tid >> 5, lid = tid & 31;
    if (lid == 0) { red0[wid] = s; red1[wid] = ss; }
    __syncthreads();
    float sum = 0.f, sumsq = 0.f;
    #pragma unroll
    for (int i = 0; i < 8; i++) { sum += red0[i]; sumsq += red1[i]; }
    float mu   = sum * (1.0f / DIM);
    float var  = sumsq * (1.0f / DIM) - mu * mu;
    float rstd = rsqrtf(var + 1e-5f);
    float4 wv = ((const float4*)w)[tid];
    float4 bv = ((const float4*)b)[tid];
    float4 o;
    o.x = (v.x - mu) * rstd * wv.x + bv.x;
    o.y = (v.y - mu) * rstd * wv.y + bv.y;
    o.z = (v.z - mu) * rstd * wv.z + bv.z;
    o.w = (v.w - mu) * rstd * wv.w + bv.w;
    ((float4*)(out + (size_t)row * DIM))[tid] = o;
}

// ---------------- SGEMM: C[M,N] = A[M,K] @ B[K,N] (+epilogue) ----------------
// EPI: 0 = +bias ; 1 = +bias, GELU(exact) ; 2 = +bias, +residual R[M,N]
// BM=BN=128, BK=8, TM=TN=8, 256 threads. All dims divisible (M=8192, K,N mult of 128).
template <int EPI>
__global__ __launch_bounds__(256)
void sgemm_kernel(int M, int N, int K,
                  const float* __restrict__ A, const float* __restrict__ B,
                  const float* __restrict__ bias, const float* __restrict__ R,
                  float* __restrict__ C) {
    const int BM = 128, BN = 128, BK = 8, TM = 8, TN = 8;
    __shared__ float As[BK][BM];
    __shared__ float Bs[BK][BN];

    int bx = blockIdx.x, by = blockIdx.y;
    int tid = threadIdx.x;

    int tcol = tid & 15;   // 16 thread-cols * 8 = 128
    int trow = tid >> 4;   // 16 thread-rows * 8 = 128

    const float* Ab = A + (size_t)by * BM * K;
    const float* Bb = B + (size_t)bx * BN;

    // A loads: 128 rows x 8 cols = 256 float4 (2 per row)
    int aRow  = tid >> 1;
    int aCol4 = (tid & 1) * 4;
    // B loads: 8 rows x 128 cols = 256 float4
    int bRow = tid >> 5;
    int bCol = (tid & 31) * 4;

    float acc[TM][TN];
    #pragma unroll
    for (int i = 0; i < TM; i++)
        #pragma unroll
        for (int j = 0; j < TN; j++) acc[i][j] = 0.f;

    for (int k0 = 0; k0 < K; k0 += BK) {
        float4 av = *(const float4*)(Ab + (size_t)aRow * K + k0 + aCol4);
        As[aCol4 + 0][aRow] = av.x;
        As[aCol4 + 1][aRow] = av.y;
        As[aCol4 + 2][aRow] = av.z;
        As[aCol4 + 3][aRow] = av.w;
        *(float4*)(&Bs[bRow][bCol]) = *(const float4*)(Bb + (size_t)(k0 + bRow) * N + bCol);
        __syncthreads();

        #pragma unroll
        for (int kk = 0; kk < BK; kk++) {
            float ra[TM], rb[TN];
            #pragma unroll
            for (int i = 0; i < TM; i += 4)
                *(float4*)(&ra[i]) = *(const float4*)(&As[kk][trow * TM + i]);
            #pragma unroll
            for (int j = 0; j < TN; j += 4)
                *(float4*)(&rb[j]) = *(const float4*)(&Bs[kk][tcol * TN + j]);
            #pragma unroll
            for (int i = 0; i < TM; i++)
                #pragma unroll
                for (int j = 0; j < TN; j++)
                    acc[i][j] = fmaf(ra[i], rb[j], acc[i][j]);
        }
        __syncthreads();
    }

    // epilogue
    int colBase = bx * BN + tcol * TN;
    float bv[TN];
    #pragma unroll
    for (int j = 0; j < TN; j += 4)
        *(float4*)(&bv[j]) = *(const float4*)(bias + colBase + j);

    #pragma unroll
    for (int i = 0; i < TM; i++) {
        int row = by * BM + trow * TM + i;
        float* crow = C + (size_t)row * N + colBase;
        const float* rrow = (EPI == 2) ? (R + (size_t)row * N + colBase) : nullptr;
        #pragma unroll
        for (int j = 0; j < TN; j += 4) {
            float4 o;
            float t0 = acc[i][j + 0] + bv[j + 0];
            float t1 = acc[i][j + 1] + bv[j + 1];
            float t2 = acc[i][j + 2] + bv[j + 2];
            float t3 = acc[i][j + 3] + bv[j + 3];
            if (EPI == 1) {
                t0 = 0.5f * t0 * (1.0f + erff(t0 * 0.70710678118654752f));
                t1 = 0.5f * t1 * (1.0f + erff(t1 * 0.70710678118654752f));
                t2 = 0.5f * t2 * (1.0f + erff(t2 * 0.70710678118654752f));
                t3 = 0.5f * t3 * (1.0f + erff(t3 * 0.70710678118654752f));
            }
            if (EPI == 2) {
                float4 rv = *(const float4*)(rrow + j);
                t0 += rv.x; t1 += rv.y; t2 += rv.z; t3 += rv.w;
            }
            o.x = t0; o.y = t1; o.z = t2; o.w = t3;
            *(float4*)(crow + j) = o;
        }
    }
}

// ---------------- causal flash attention, fp32 ----------------
// grid: (S/128 q-tiles, B*HEADS). block: 128 threads, 1 query row per thread.
__global__ __launch_bounds__(128)
void attn_kernel(const float* __restrict__ qkv, float* __restrict__ out) {
    int qt  = blockIdx.x;          // 0..15
    int bh  = blockIdx.y;          // 0..63
    int b   = bh >> 4;
    int h   = bh & 15;
    int tid = threadIdx.x;
    int rowseq = qt * 128 + tid;   // query position within sequence
    size_t t   = (size_t)b * SS + rowseq;

    const float* qptr = qkv + t * (3 * DIM) + h * HDIM;
    float q[HDIM];
    #pragma unroll
    for (int d = 0; d < HDIM; d++) q[d] = qptr[d];

    __shared__ float Ks[64][HDIM];
    __shared__ float Vs[64][HDIM];

    float acc[HDIM];
    #pragma unroll
    for (int d = 0; d < HDIM; d++) acc[d] = 0.f;
    float m = -1e30f, l = 0.f;
    const float scale = 0.125f;  // 64^-0.5

    int ntiles = 2 * qt + 2;     // key tiles of 64 covering rows [0, qt*128+128)
    for (int jt = 0; jt < ntiles; jt++) {
        __syncthreads();
        // cooperative load: 64 keys x 64 dims (K and V), float4 coalesced
        #pragma unroll
        for (int i = 0; i < 8; i++) {
            int idx = i * 128 + tid;        // 0..1023
            int r   = idx >> 4;
            int c4  = (idx & 15) * 4;
            const float* kp = qkv + ((size_t)b * SS + jt * 64 + r) * (3 * DIM)
                              + DIM + h * HDIM + c4;
            *(float4*)&Ks[r][c4] = *(const float4*)kp;
            *(float4*)&Vs[r][c4] = *(const float4*)(kp + DIM);
        }
        __syncthreads();

        float s[64];
        float tmax = -1e30f;
        #pragma unroll
        for (int j = 0; j < 64; j++) {
            float dot = 0.f;
            #pragma unroll
            for (int d = 0; d < HDIM; d++)
                dot = fmaf(q[d], Ks[j][d], dot);
            int kidx = jt * 64 + j;
            s[j] = (kidx <= rowseq) ? dot * scale : -1e30f;
            tmax = fmaxf(tmax, s[j]);
        }
        float mnew = fmaxf(m, tmax);
        float corr = __expf(m - mnew);
        l *= corr;
        #pragma unroll
        for (int d = 0; d < HDIM; d++) acc[d] *= corr;
        #pragma unroll
        for (int j = 0; j < 64; j++) {
            float p = __expf(s[j] - mnew);
            l += p;
            #pragma unroll
            for (int d = 0; d < HDIM; d++)
                acc[d] = fmaf(p, Vs[j][d], acc[d]);
        }
        m = mnew;
    }

    float inv = 1.0f / l;
    float* op = out + t * DIM + h * HDIM;
    #pragma unroll
    for (int d = 0; d < HDIM; d++) op[d] = acc[d] * inv;
}

// ---------------- launch ----------------
extern "C" void kernel_launch(void* const* d_in, const int* in_sizes, int n_in,
                              void* d_out, int out_size) {
    const float* x      = (const float*)d_in[0];
    const float* ln1_w  = (const float*)d_in[1];
    const float* ln1_b  = (const float*)d_in[2];
    const float* qkv_w  = (const float*)d_in[3];
    const float* qkv_b  = (const float*)d_in[4];
    const float* proj_w = (const float*)d_in[5];
    const float* proj_b = (const float*)d_in[6];
    const float* ln2_w  = (const float*)d_in[7];
    const float* ln2_b  = (const float*)d_in[8];
    const float* fc1_w  = (const float*)d_in[9];
    const float* fc1_b  = (const float*)d_in[10];
    const float* fc2_w  = (const float*)d_in[11];
    const float* fc2_b  = (const float*)d_in[12];
    float* out = (float*)d_out;

    float *xn, *qkv, *attn, *x1, *h;
    cudaGetSymbolAddress((void**)&xn,   g_xn);
    cudaGetSymbolAddress((void**)&qkv,  g_qkv);
    cudaGetSymbolAddress((void**)&attn, g_attn);
    cudaGetSymbolAddress((void**)&x1,   g_x1);
    cudaGetSymbolAddress((void**)&h,    g_h);

    // 1. LN1
    ln_kernel<<<TT, 256>>>(x, ln1_w, ln1_b, xn);
    // 2. QKV = xn @ qkv_w + qkv_b          [8192 x 3072]
    {
        dim3 g(3 * DIM / 128, TT / 128);
        sgemm_kernel<0><<<g, 256>>>(TT, 3 * DIM, DIM, xn, qkv_w, qkv_b, nullptr, qkv);
    }
    // 3. causal attention                   [8192 x 1024]
    {
        dim3 g(SS / 128, BB * HEADS);
        attn_kernel<<<g, 128>>>(qkv, attn);
    }
    // 4. x1 = x + attn @ proj_w + proj_b
    {
        dim3 g(DIM / 128, TT / 128);
        sgemm_kernel<2><<<g, 256>>>(TT, DIM, DIM, attn, proj_w, proj_b, x, x1);
    }
    // 5. LN2
    ln_kernel<<<TT, 256>>>(x1, ln2_w, ln2_b, xn);
    // 6. h = gelu(xn @ fc1_w + fc1_b)       [8192 x 4096]
    {
        dim3 g(MLP / 128, TT / 128);
        sgemm_kernel<1><<<g, 256>>>(TT, MLP, DIM, xn, fc1_w, fc1_b, nullptr, h);
    }
    // 7. out = x1 + h @ fc2_w + fc2_b
    {
        dim3 g(DIM / 128, TT / 128);
        sgemm_kernel<2><<<g, 256>>>(TT, DIM, MLP, h, fc2_w, fc2_b, x1, out);
    }
}

// round 3
// speedup vs baseline: 1.5992x; 1.5992x over previous
#include <cuda_runtime.h>
#include <math.h>
#include <stdint.h>

#define DIM   1024
#define HEADS 16
#define HDIM  64
#define MLP   4096
#define BB    4
#define SS    2048
#define TT    (BB*SS)   // 8192 tokens

// ---------------- scratch (device globals; no allocation) ----------------
__device__ float g_xn[(size_t)TT*DIM];
__device__ float g_qkv[(size_t)TT*3*DIM];
__device__ float g_attn[(size_t)TT*DIM];
__device__ float g_x1[(size_t)TT*DIM];
__device__ float g_h[(size_t)TT*MLP];
// transposed (tf32-rounded) weights, [N,K] K-major
__device__ float g_qkvT[(size_t)3*DIM*DIM];
__device__ float g_projT[(size_t)DIM*DIM];
__device__ float g_fc1T[(size_t)MLP*DIM];
__device__ float g_fc2T[(size_t)DIM*MLP];

// ---------------- helpers ----------------
__device__ __forceinline__ float tf32_rn(float x) {
    uint32_t u;
    asm("cvt.rna.tf32.f32 %0, %1;" : "=r"(u) : "f"(x));
    return __uint_as_float(u);
}

__device__ __forceinline__ void mma_tf32(float* c, const uint32_t* a, const uint32_t* b) {
    asm volatile(
        "mma.sync.aligned.m16n8k8.row.col.f32.tf32.tf32.f32 "
        "{%0,%1,%2,%3}, {%4,%5,%6,%7}, {%8,%9}, {%0,%1,%2,%3};"
        : "+f"(c[0]), "+f"(c[1]), "+f"(c[2]), "+f"(c[3])
        : "r"(a[0]), "r"(a[1]), "r"(a[2]), "r"(a[3]), "r"(b[0]), "r"(b[1]));
}

// ---------------- LayerNorm (tf32-rounded output) ----------------
__global__ __launch_bounds__(256)
void ln_kernel(const float* __restrict__ x, const float* __restrict__ w,
               const float* __restrict__ b, float* __restrict__ out) {
    int row = blockIdx.x;
    int tid = threadIdx.x;
    const float4* xr = (const float4*)(x + (size_t)row * DIM);
    float4 v = xr[tid];
    float s  = v.x + v.y + v.z + v.w;
    float ss = v.x*v.x + v.y*v.y + v.z*v.z + v.w*v.w;
    #pragma unroll
    for (int o = 16; o; o >>= 1) {
        s  += __shfl_xor_sync(0xffffffffu, s,  o);
        ss += __shfl_xor_sync(0xffffffffu, ss, o);
    }
    __shared__ float red0[8], red1[8];
    int wid = tid >> 5, lid = tid & 31;
    if (lid == 0) { red0[wid] = s; red1[wid] = ss; }
    __syncthreads();
    float sum = 0.f, sumsq = 0.f;
    #pragma unroll
    for (int i = 0; i < 8; i++) { sum += red0[i]; sumsq += red1[i]; }
    float mu   = sum * (1.0f / DIM);
    float var  = sumsq * (1.0f / DIM) - mu * mu;
    float rstd = rsqrtf(var + 1e-5f);
    float4 wv = ((const float4*)w)[tid];
    float4 bv = ((const float4*)b)[tid];
    float4 o;
    o.x = tf32_rn((v.x - mu) * rstd * wv.x + bv.x);
    o.y = tf32_rn((v.y - mu) * rstd * wv.y + bv.y);
    o.z = tf32_rn((v.z - mu) * rstd * wv.z + bv.z);
    o.w = tf32_rn((v.w - mu) * rstd * wv.w + bv.w);
    ((float4*)(out + (size_t)row * DIM))[tid] = o;
}

// ---------------- weight transpose [K,N] -> [N,K] with tf32 rounding ----------------
__global__ __launch_bounds__(256)
void transpose_rn_kernel(const float* __restrict__ in, float* __restrict__ out,
                         int K, int N) {
    __shared__ float tile[32][33];
    int bx = blockIdx.x;  // N/32
    int by = blockIdx.y;  // K/32
    int tx = threadIdx.x & 31;
    int ty = threadIdx.x >> 5;  // 0..7
    #pragma unroll
    for (int i = 0; i < 32; i += 8)
        tile[ty + i][tx] = in[(size_t)(by * 32 + ty + i) * N + bx * 32 + tx];
    __syncthreads();
    #pragma unroll
    for (int i = 0; i < 32; i += 8)
        out[(size_t)(bx * 32 + ty + i) * K + by * 32 + tx] = tf32_rn(tile[tx][ty + i]);
}

// ---------------- tf32 mma.sync GEMM: C[M,N] = A[M,K] @ Bt[N,K]^T (+epi) ----------------
// EPI: 0 = +bias ; 1 = +bias, GELU, tf32-round ; 2 = +bias, +residual
// BM=BN=128, BK=32, 256 threads (8 warps: 4 along M x 2 along N), warp tile 32x64.
#define BM 128
#define BN 128
#define BK 32
#define LDA 36   // padded row length (floats) for conflict-free fragment loads
#define SMEM_BUF_FLOATS (BM * LDA)            // per operand per buffer
#define SMEM_TOTAL_BYTES (4 * SMEM_BUF_FLOATS * 4)   // A0,B0,A1,B1

template <int EPI>
__global__ __launch_bounds__(256, 1)
void gemm_mma(int M, int N, int K,
              const float* __restrict__ A, const float* __restrict__ Bt,
              const float* __restrict__ bias, const float* __restrict__ R,
              float* __restrict__ C) {
    extern __shared__ float smem[];
    float* As[2] = { smem,                        smem + 2 * SMEM_BUF_FLOATS };
    float* Bs[2] = { smem + SMEM_BUF_FLOATS,      smem + 3 * SMEM_BUF_FLOATS };

    int tid  = threadIdx.x;
    int wid  = tid >> 5;
    int lane = tid & 31;
    int gid  = lane >> 2;   // group id 0..7
    int tg   = lane & 3;    // thread-in-group 0..3
    int warpM = wid & 3;    // 0..3
    int warpN = wid >> 2;   // 0..1
    int bx = blockIdx.x, by = blockIdx.y;

    const float* Ablk = A  + (size_t)(by * BM) * K;
    const float* Bblk = Bt + (size_t)(bx * BN) * K;

    // gmem load mapping: 1024 float4 per tile, 4 per thread
    int ldRow = tid >> 1;          // wrong for 4-per-thread; use idx below
    (void)ldRow;

    float acc[2][8][4];
    #pragma unroll
    for (int i = 0; i < 2; i++)
        #pragma unroll
        for (int j = 0; j < 8; j++)
            #pragma unroll
            for (int c = 0; c < 4; c++) acc[i][j][c] = 0.f;

    float4 pa[4], pb[4];

    // prefetch k-chunk 0
    #pragma unroll
    for (int it = 0; it < 4; it++) {
        int idx = it * 256 + tid;
        int r = idx >> 3, c4 = (idx & 7) * 4;
        pa[it] = *(const float4*)(Ablk + (size_t)r * K + c4);
        pb[it] = *(const float4*)(Bblk + (size_t)r * K + c4);
    }
    #pragma unroll
    for (int it = 0; it < 4; it++) {
        int idx = it * 256 + tid;
        int r = idx >> 3, c4 = (idx & 7) * 4;
        *(float4*)(As[0] + r * LDA + c4) = pa[it];
        *(float4*)(Bs[0] + r * LDA + c4) = pb[it];
    }
    __syncthreads();

    int NC = K / BK;
    for (int kc = 0; kc < NC; kc++) {
        int buf = kc & 1;
        bool has_next = (kc + 1 < NC);
        if (has_next) {
            int kb = (kc + 1) * BK;
            #pragma unroll
            for (int it = 0; it < 4; it++) {
                int idx = it * 256 + tid;
                int r = idx >> 3, c4 = (idx & 7) * 4;
                pa[it] = *(const float4*)(Ablk + (size_t)r * K + kb + c4);
                pb[it] = *(const float4*)(Bblk + (size_t)r * K + kb + c4);
            }
        }

        const float* Ab = As[buf];
        const float* Bb = Bs[buf];
        #pragma unroll
        for (int kk = 0; kk < BK; kk += 8) {
            uint32_t af[2][4];
            #pragma unroll
            for (int i = 0; i < 2; i++) {
                const float* ap = Ab + (warpM * 32 + i * 16 + gid) * LDA + kk + tg;
                af[i][0] = __float_as_uint(ap[0]);
                af[i][1] = __float_as_uint(ap[8 * LDA]);
                af[i][2] = __float_as_uint(ap[4]);
                af[i][3] = __float_as_uint(ap[8 * LDA + 4]);
            }
            uint32_t bf[8][2];
            #pragma unroll
            for (int j = 0; j < 8; j++) {
                const float* bp = Bb + (warpN * 64 + j * 8 + gid) * LDA + kk + tg;
                bf[j][0] = __float_as_uint(bp[0]);
                bf[j][1] = __float_as_uint(bp[4]);
            }
            #pragma unroll
            for (int i = 0; i < 2; i++)
                #pragma unroll
                for (int j = 0; j < 8; j++)
                    mma_tf32(acc[i][j], af[i], bf[j]);
        }

        if (has_next) {
            int nb = buf ^ 1;
            #pragma unroll
            for (int it = 0; it < 4; it++) {
                int idx = it * 256 + tid;
                int r = idx >> 3, c4 = (idx & 7) * 4;
                *(float4*)(As[nb] + r * LDA + c4) = pa[it];
                *(float4*)(Bs[nb] + r * LDA + c4) = pb[it];
            }
            __syncthreads();
        }
    }

    // epilogue
    int colW = bx * BN + warpN * 64;
    #pragma unroll
    for (int i = 0; i < 2; i++) {
        #pragma unroll
        for (int r2 = 0; r2 < 2; r2++) {
            int row = by * BM + warpM * 32 + i * 16 + gid + r2 * 8;
            float*       crow = C + (size_t)row * N + colW;
            const float* rrow = (EPI == 2) ? (R + (size_t)row * N + colW) : nullptr;
            #pragma unroll
            for (int j = 0; j < 8; j++) {
                int col = j * 8 + 2 * tg;
                float t0 = acc[i][j][r2 * 2 + 0] + bias[colW + col];
                float t1 = acc[i][j][r2 * 2 + 1] + bias[colW + col + 1];
                if (EPI == 1) {
                    t0 = 0.5f * t0 * (1.0f + erff(t0 * 0.70710678118654752f));
                    t1 = 0.5f * t1 * (1.0f + erff(t1 * 0.70710678118654752f));
                    t0 = tf32_rn(t0);
                    t1 = tf32_rn(t1);
                }
                if (EPI == 2) {
                    float2 rv = *(const float2*)(rrow + col);
                    t0 += rv.x; t1 += rv.y;
                }
                *(float2*)(crow + col) = make_float2(t0, t1);
            }
        }
    }
}

// ---------------- causal flash attention, fp32 (tf32-rounded output) ----------------
__global__ __launch_bounds__(128)
void attn_kernel(const float* __restrict__ qkv, float* __restrict__ out) {
    int qt  = blockIdx.x;
    int bh  = blockIdx.y;
    int b   = bh >> 4;
    int h   = bh & 15;
    int tid = threadIdx.x;
    int rowseq = qt * 128 + tid;
    size_t t   = (size_t)b * SS + rowseq;

    const float* qptr = qkv + t * (3 * DIM) + h * HDIM;
    float q[HDIM];
    #pragma unroll
    for (int d = 0; d < HDIM; d++) q[d] = qptr[d];

    __shared__ float Ks[64][HDIM];
    __shared__ float Vs[64][HDIM];

    float acc[HDIM];
    #pragma unroll
    for (int d = 0; d < HDIM; d++) acc[d] = 0.f;
    float m = -1e30f, l = 0.f;
    const float scale = 0.125f;

    int ntiles = 2 * qt + 2;
    for (int jt = 0; jt < ntiles; jt++) {
        __syncthreads();
        #pragma unroll
        for (int i = 0; i < 8; i++) {
            int idx = i * 128 + tid;
            int r   = idx >> 4;
            int c4  = (idx & 15) * 4;
            const float* kp = qkv + ((size_t)b * SS + jt * 64 + r) * (3 * DIM)
                              + DIM + h * HDIM + c4;
            *(float4*)&Ks[r][c4] = *(const float4*)kp;
            *(float4*)&Vs[r][c4] = *(const float4*)(kp + DIM);
        }
        __syncthreads();

        float s[64];
        float tmax = -1e30f;
        #pragma unroll
        for (int j = 0; j < 64; j++) {
            float dot = 0.f;
            #pragma unroll
            for (int d = 0; d < HDIM; d++)
                dot = fmaf(q[d], Ks[j][d], dot);
            int kidx = jt * 64 + j;
            s[j] = (kidx <= rowseq) ? dot * scale : -1e30f;
            tmax = fmaxf(tmax, s[j]);
        }
        float mnew = fmaxf(m, tmax);
        float corr = __expf(m - mnew);
        l *= corr;
        #pragma unroll
        for (int d = 0; d < HDIM; d++) acc[d] *= corr;
        #pragma unroll
        for (int j = 0; j < 64; j++) {
            float p = __expf(s[j] - mnew);
            l += p;
            #pragma unroll
            for (int d = 0; d < HDIM; d++)
                acc[d] = fmaf(p, Vs[j][d], acc[d]);
        }
        m = mnew;
    }

    float inv = 1.0f / l;
    float* op = out + t * DIM + h * HDIM;
    #pragma unroll
    for (int d = 0; d < HDIM; d++) op[d] = tf32_rn(acc[d] * inv);
}

// ---------------- launch ----------------
extern "C" void kernel_launch(void* const* d_in, const int* in_sizes, int n_in,
                              void* d_out, int out_size) {
    const float* x      = (const float*)d_in[0];
    const float* ln1_w  = (const float*)d_in[1];
    const float* ln1_b  = (const float*)d_in[2];
    const float* qkv_w  = (const float*)d_in[3];
    const float* qkv_b  = (const float*)d_in[4];
    const float* proj_w = (const float*)d_in[5];
    const float* proj_b = (const float*)d_in[6];
    const float* ln2_w  = (const float*)d_in[7];
    const float* ln2_b  = (const float*)d_in[8];
    const float* fc1_w  = (const float*)d_in[9];
    const float* fc1_b  = (const float*)d_in[10];
    const float* fc2_w  = (const float*)d_in[11];
    const float* fc2_b  = (const float*)d_in[12];
    float* out = (float*)d_out;

    float *xn, *qkv, *attn, *x1, *h, *qkvT, *projT, *fc1T, *fc2T;
    cudaGetSymbolAddress((void**)&xn,    g_xn);
    cudaGetSymbolAddress((void**)&qkv,   g_qkv);
    cudaGetSymbolAddress((void**)&attn,  g_attn);
    cudaGetSymbolAddress((void**)&x1,    g_x1);
    cudaGetSymbolAddress((void**)&h,     g_h);
    cudaGetSymbolAddress((void**)&qkvT,  g_qkvT);
    cudaGetSymbolAddress((void**)&projT, g_projT);
    cudaGetSymbolAddress((void**)&fc1T,  g_fc1T);
    cudaGetSymbolAddress((void**)&fc2T,  g_fc2T);

    static bool attr_done = false;
    if (!attr_done) {
        cudaFuncSetAttribute(gemm_mma<0>, cudaFuncAttributeMaxDynamicSharedMemorySize, SMEM_TOTAL_BYTES);
        cudaFuncSetAttribute(gemm_mma<1>, cudaFuncAttributeMaxDynamicSharedMemorySize, SMEM_TOTAL_BYTES);
        cudaFuncSetAttribute(gemm_mma<2>, cudaFuncAttributeMaxDynamicSharedMemorySize, SMEM_TOTAL_BYTES);
        attr_done = true;
    }

    // weight transposes (tf32-rounded), [K,N] -> [N,K]
    transpose_rn_kernel<<<dim3(3*DIM/32, DIM/32), 256>>>(qkv_w, qkvT, DIM, 3*DIM);
    transpose_rn_kernel<<<dim3(DIM/32, DIM/32), 256>>>(proj_w, projT, DIM, DIM);
    transpose_rn_kernel<<<dim3(MLP/32, DIM/32), 256>>>(fc1_w, fc1T, DIM, MLP);
    transpose_rn_kernel<<<dim3(DIM/32, MLP/32), 256>>>(fc2_w, fc2T, MLP, DIM);

    // 1. LN1
    ln_kernel<<<TT, 256>>>(x, ln1_w, ln1_b, xn);
    // 2. QKV = xn @ qkv_w + qkv_b
    gemm_mma<0><<<dim3(3*DIM/BN, TT/BM), 256, SMEM_TOTAL_BYTES>>>(TT, 3*DIM, DIM, xn, qkvT, qkv_b, nullptr, qkv);
    // 3. causal attention
    attn_kernel<<<dim3(SS/128, BB*HEADS), 128>>>(qkv, attn);
    // 4. x1 = x + attn @ proj_w + proj_b
    gemm_mma<2><<<dim3(DIM/BN, TT/BM), 256, SMEM_TOTAL_BYTES>>>(TT, DIM, DIM, attn, projT, proj_b, x, x1);
    // 5. LN2
    ln_kernel<<<TT, 256>>>(x1, ln2_w, ln2_b, xn);
    // 6. h = gelu(xn @ fc1_w + fc1_b)  (tf32-rounded)
    gemm_mma<1><<<dim3(MLP/BN, TT/BM), 256, SMEM_TOTAL_BYTES>>>(TT, MLP, DIM, xn, fc1T, fc1_b, nullptr, h);
    // 7. out = x1 + h @ fc2_w + fc2_b
    gemm_mma<2><<<dim3(DIM/BN, TT/BM), 256, SMEM_TOTAL_BYTES>>>(TT, DIM, MLP, h, fc2T, fc2_b, x1, out);
}

// round 4
// speedup vs baseline: 7.3120x; 4.5722x over previous
#include <cuda_runtime.h>
#include <cuda_fp16.h>
#include <math.h>
#include <stdint.h>

#define DIM   1024
#define HEADS 16
#define HDIM  64
#define MLP   4096
#define BB    4
#define SS    2048
#define TT    (BB*SS)   // 8192 tokens

// ---------------- scratch (device globals; no allocation) ----------------
__device__ __half h_xn[(size_t)TT*DIM];
__device__ __half h_qkv[(size_t)TT*3*DIM];
__device__ __half h_attn[(size_t)TT*DIM];
__device__ float  g_x1[(size_t)TT*DIM];
__device__ __half h_h[(size_t)TT*MLP];
__device__ __half h_qkvT[(size_t)3*DIM*DIM];
__device__ __half h_projT[(size_t)DIM*DIM];
__device__ __half h_fc1T[(size_t)DIM*MLP];
__device__ __half h_fc2T[(size_t)MLP*DIM];
__device__ __half h_vT[(size_t)BB*HEADS*HDIM*SS];

// ---------------- mma helper ----------------
__device__ __forceinline__ void mma_f16(float* c, const uint32_t* a, const uint32_t* b) {
    asm volatile(
        "mma.sync.aligned.m16n8k16.row.col.f32.f16.f16.f32 "
        "{%0,%1,%2,%3}, {%4,%5,%6,%7}, {%8,%9}, {%0,%1,%2,%3};"
        : "+f"(c[0]), "+f"(c[1]), "+f"(c[2]), "+f"(c[3])
        : "r"(a[0]), "r"(a[1]), "r"(a[2]), "r"(a[3]), "r"(b[0]), "r"(b[1]));
}

// ---------------- LayerNorm: fp32 in -> fp16 out ----------------
__global__ __launch_bounds__(256)
void ln_kernel(const float* __restrict__ x, const float* __restrict__ w,
               const float* __restrict__ b, __half* __restrict__ out) {
    int row = blockIdx.x;
    int tid = threadIdx.x;
    const float4* xr = (const float4*)(x + (size_t)row * DIM);
    float4 v = xr[tid];
    float s  = v.x + v.y + v.z + v.w;
    float ss = v.x*v.x + v.y*v.y + v.z*v.z + v.w*v.w;
    #pragma unroll
    for (int o = 16; o; o >>= 1) {
        s  += __shfl_xor_sync(0xffffffffu, s,  o);
        ss += __shfl_xor_sync(0xffffffffu, ss, o);
    }
    __shared__ float red0[8], red1[8];
    int wid = tid >> 5, lid = tid & 31;
    if (lid == 0) { red0[wid] = s; red1[wid] = ss; }
    __syncthreads();
    float sum = 0.f, sumsq = 0.f;
    #pragma unroll
    for (int i = 0; i < 8; i++) { sum += red0[i]; sumsq += red1[i]; }
    float mu   = sum * (1.0f / DIM);
    float var  = sumsq * (1.0f / DIM) - mu * mu;
    float rstd = rsqrtf(var + 1e-5f);
    float4 wv = ((const float4*)w)[tid];
    float4 bv = ((const float4*)b)[tid];
    __half2* o2 = (__half2*)(out + (size_t)row * DIM);
    o2[tid*2+0] = __floats2half2_rn((v.x - mu)*rstd*wv.x + bv.x,
                                    (v.y - mu)*rstd*wv.y + bv.y);
    o2[tid*2+1] = __floats2half2_rn((v.z - mu)*rstd*wv.z + bv.z,
                                    (v.w - mu)*rstd*wv.w + bv.w);
}

// ---------------- weight transpose [K,N] fp32 -> [N,K] fp16 ----------------
__global__ __launch_bounds__(256)
void transpose_h_kernel(const float* __restrict__ in, __half* __restrict__ out,
                        int K, int N) {
    __shared__ float tile[32][33];
    int bx = blockIdx.x;  // N/32
    int by = blockIdx.y;  // K/32
    int tx = threadIdx.x & 31;
    int ty = threadIdx.x >> 5;  // 0..7
    #pragma unroll
    for (int i = 0; i < 32; i += 8)
        tile[ty + i][tx] = in[(size_t)(by * 32 + ty + i) * N + bx * 32 + tx];
    __syncthreads();
    #pragma unroll
    for (int i = 0; i < 32; i += 8)
        out[(size_t)(bx * 32 + ty + i) * K + by * 32 + tx] = __float2half_rn(tile[tx][ty + i]);
}

// ---------------- V transpose: h_qkv V-part [token][dim] -> h_vT [bh][dim][seq] ----------------
__global__ __launch_bounds__(256)
void vt_kernel(const __half* __restrict__ qkv, __half* __restrict__ vT) {
    __shared__ __half t[32][33];
    int s0 = blockIdx.x * 32;
    int d0 = blockIdx.y * 32;
    int bh = blockIdx.z;
    int b = bh >> 4, h = bh & 15;
    int tx = threadIdx.x & 31, ty = threadIdx.x >> 5;
    #pragma unroll
    for (int i = 0; i < 32; i += 8)
        t[ty + i][tx] = qkv[((size_t)(b*SS) + s0 + ty + i) * (3*DIM) + 2*DIM + h*HDIM + d0 + tx];
    __syncthreads();
    #pragma unroll
    for (int i = 0; i < 32; i += 8)
        vT[((size_t)bh * HDIM + d0 + ty + i) * SS + s0 + tx] = t[tx][ty + i];
}

// ---------------- fp16 mma GEMM: C[M,N] = A[M,K] @ Bt[N,K]^T (+epi) ----------------
// EPI: 0 = +bias -> half ; 1 = +bias, GELU -> half ; 2 = +bias, +residual -> float
// BM=BN=128, BK=32, 128 threads (4 warps, warp tile 64x64), double buffered.
#define GLDA 40   // halves per smem row (pad 8)

template <int EPI>
__global__ __launch_bounds__(128, 2)
void gemm_h(int M, int N, int K,
            const __half* __restrict__ A, const __half* __restrict__ Bt,
            const float* __restrict__ bias, const float* __restrict__ R,
            void* __restrict__ Cout) {
    __shared__ __half sh[4 * 128 * GLDA];
    __half* As[2] = { sh,                sh + 2 * 128 * GLDA };
    __half* Bs[2] = { sh + 128 * GLDA,   sh + 3 * 128 * GLDA };

    int tid = threadIdx.x;
    int wid = tid >> 5, lane = tid & 31;
    int gid = lane >> 2, tg = lane & 3;
    int wm = wid & 1, wn = wid >> 1;       // warp grid 2 (M) x 2 (N)
    int bx = blockIdx.x, by = blockIdx.y;

    const __half* Ab = A  + (size_t)(by * 128) * K;
    const __half* Bb = Bt + (size_t)(bx * 128) * K;

    float acc[4][8][4];
    #pragma unroll
    for (int i = 0; i < 4; i++)
        #pragma unroll
        for (int j = 0; j < 8; j++)
            #pragma unroll
            for (int c = 0; c < 4; c++) acc[i][j][c] = 0.f;

    int4 pa[4], pb[4];
    // prefetch chunk 0
    #pragma unroll
    for (int it = 0; it < 4; it++) {
        int idx = it * 128 + tid;
        int r = idx >> 2, c8 = (idx & 3) * 8;
        pa[it] = *(const int4*)(Ab + (size_t)r * K + c8);
        pb[it] = *(const int4*)(Bb + (size_t)r * K + c8);
    }
    #pragma unroll
    for (int it = 0; it < 4; it++) {
        int idx = it * 128 + tid;
        int r = idx >> 2, c8 = (idx & 3) * 8;
        *(int4*)(As[0] + r * GLDA + c8) = pa[it];
        *(int4*)(Bs[0] + r * GLDA + c8) = pb[it];
    }
    __syncthreads();

    int NC = K / 32;
    for (int kc = 0; kc < NC; kc++) {
        int buf = kc & 1;
        bool has_next = (kc + 1 < NC);
        if (has_next) {
            int kb = (kc + 1) * 32;
            #pragma unroll
            for (int it = 0; it < 4; it++) {
                int idx = it * 128 + tid;
                int r = idx >> 2, c8 = (idx & 3) * 8;
                pa[it] = *(const int4*)(Ab + (size_t)r * K + kb + c8);
                pb[it] = *(const int4*)(Bb + (size_t)r * K + kb + c8);
            }
        }
        const __half* Ac = As[buf];
        const __half* Bc = Bs[buf];
        #pragma unroll
        for (int kk = 0; kk < 32; kk += 16) {
            uint32_t af[4][4];
            #pragma unroll
            for (int mf = 0; mf < 4; mf++) {
                const __half* p = Ac + (wm * 64 + mf * 16 + gid) * GLDA + kk + 2 * tg;
                af[mf][0] = *(const uint32_t*)(p);
                af[mf][1] = *(const uint32_t*)(p + 8 * GLDA);
                af[mf][2] = *(const uint32_t*)(p + 8);
                af[mf][3] = *(const uint32_t*)(p + 8 * GLDA + 8);
            }
            uint32_t bf[8][2];
            #pragma unroll
            for (int nb = 0; nb < 8; nb++) {
                const __half* p = Bc + (wn * 64 + nb * 8 + gid) * GLDA + kk + 2 * tg;
                bf[nb][0] = *(const uint32_t*)(p);
                bf[nb][1] = *(const uint32_t*)(p + 8);
            }
            #pragma unroll
            for (int mf = 0; mf < 4; mf++)
                #pragma unroll
                for (int nb = 0; nb < 8; nb++)
                    mma_f16(acc[mf][nb], af[mf], bf[nb]);
        }
        if (has_next) {
            int nbuf = buf ^ 1;
            #pragma unroll
            for (int it = 0; it < 4; it++) {
                int idx = it * 128 + tid;
                int r = idx >> 2, c8 = (idx & 3) * 8;
                *(int4*)(As[nbuf] + r * GLDA + c8) = pa[it];
                *(int4*)(Bs[nbuf] + r * GLDA + c8) = pb[it];
            }
            __syncthreads();
        }
    }

    // epilogue
    int colW = bx * 128 + wn * 64;
    #pragma unroll
    for (int mf = 0; mf < 4; mf++) {
        #pragma unroll
        for (int r2 = 0; r2 < 2; r2++) {
            int row = by * 128 + wm * 64 + mf * 16 + gid + r2 * 8;
            #pragma unroll
            for (int nb = 0; nb < 8; nb++) {
                int gcol = colW + nb * 8 + 2 * tg;
                float t0 = acc[mf][nb][r2 * 2 + 0] + bias[gcol];
                float t1 = acc[mf][nb][r2 * 2 + 1] + bias[gcol + 1];
                if (EPI == 1) {
                    t0 = 0.5f * t0 * (1.0f + erff(t0 * 0.70710678118654752f));
                    t1 = 0.5f * t1 * (1.0f + erff(t1 * 0.70710678118654752f));
                }
                if (EPI == 2) {
                    float2 rv = *(const float2*)(R + (size_t)row * N + gcol);
                    t0 += rv.x; t1 += rv.y;
                    *(float2*)((float*)Cout + (size_t)row * N + gcol) = make_float2(t0, t1);
                } else {
                    *(__half2*)((__half*)Cout + (size_t)row * N + gcol) = __floats2half2_rn(t0, t1);
                }
            }
        }
    }
}

// ---------------- causal flash attention with fp16 mma ----------------
// grid (S/64 q-tiles, B*H). 128 threads = 4 warps, each warp 16 q-rows.
#define KLD 72   // smem row stride in halves (pad => bank = 4*gid+tg, conflict-free)

__global__ __launch_bounds__(128)
void attn_mma(const __half* __restrict__ qkv, const __half* __restrict__ vT,
              __half* __restrict__ out) {
    int qt = blockIdx.x, bh = blockIdx.y;
    int b = bh >> 4, h = bh & 15;
    int tid = threadIdx.x;
    int wid = tid >> 5, lane = tid & 31;
    int gid = lane >> 2, tg = lane & 3;
    int q0 = qt * 64;

    __shared__ __half Ks[64 * KLD];
    __shared__ __half Vt[64 * KLD];   // [dim][key]

    // Q a-fragments (kept in registers for all K-tiles)
    uint32_t qa[4][4];
    {
        const __half* Q0 = qkv + ((size_t)(b * SS) + q0 + wid * 16 + gid) * (3 * DIM) + h * HDIM + 2 * tg;
        const __half* Q1 = Q0 + (size_t)8 * (3 * DIM);
        #pragma unroll
        for (int kcc = 0; kcc < 4; kcc++) {
            qa[kcc][0] = *(const uint32_t*)(Q0 + kcc * 16);
            qa[kcc][1] = *(const uint32_t*)(Q1 + kcc * 16);
            qa[kcc][2] = *(const uint32_t*)(Q0 + kcc * 16 + 8);
            qa[kcc][3] = *(const uint32_t*)(Q1 + kcc * 16 + 8);
        }
    }

    float oacc[8][4];
    #pragma unroll
    for (int nb = 0; nb < 8; nb++)
        #pragma unroll
        for (int c = 0; c < 4; c++) oacc[nb][c] = 0.f;
    float m0 = -1e30f, m1 = -1e30f, l0 = 0.f, l1 = 0.f;
    int rg0 = q0 + wid * 16 + gid;
    int rg1 = rg0 + 8;

    for (int jt = 0; jt <= qt; jt++) {
        __syncthreads();
        #pragma unroll
        for (int it = 0; it < 4; it++) {
            int idx = it * 128 + tid;
            int r = idx >> 3, c8 = (idx & 7) * 8;
            *(int4*)(Ks + r * KLD + c8) =
                *(const int4*)(qkv + ((size_t)(b * SS) + jt * 64 + r) * (3 * DIM) + DIM + h * HDIM + c8);
            *(int4*)(Vt + r * KLD + c8) =
                *(const int4*)(vT + ((size_t)bh * HDIM + r) * SS + jt * 64 + c8);
        }
        __syncthreads();

        // S = Q @ K^T
        float sacc[8][4];
        #pragma unroll
        for (int nb = 0; nb < 8; nb++)
            #pragma unroll
            for (int c = 0; c < 4; c++) sacc[nb][c] = 0.f;
        #pragma unroll
        for (int kcc = 0; kcc < 4; kcc++) {
            #pragma unroll
            for (int nb = 0; nb < 8; nb++) {
                const __half* p = Ks + (nb * 8 + gid) * KLD + kcc * 16 + 2 * tg;
                uint32_t bb[2] = { *(const uint32_t*)p, *(const uint32_t*)(p + 8) };
                mma_f16(sacc[nb], qa[kcc], bb);
            }
        }

        // scale + causal mask + row max
        const float sc = 0.125f;
        float tm0 = -1e30f, tm1 = -1e30f;
        #pragma unroll
        for (int nb = 0; nb < 8; nb++) {
            int col = jt * 64 + nb * 8 + 2 * tg;
            float s0 = sacc[nb][0] * sc, s1 = sacc[nb][1] * sc;
            float s2 = sacc[nb][2] * sc, s3 = sacc[nb][3] * sc;
            if (jt == qt) {
                if (col     > rg0) s0 = -1e30f;
                if (col + 1 > rg0) s1 = -1e30f;
                if (col     > rg1) s2 = -1e30f;
                if (col + 1 > rg1) s3 = -1e30f;
            }
            sacc[nb][0] = s0; sacc[nb][1] = s1; sacc[nb][2] = s2; sacc[nb][3] = s3;
            tm0 = fmaxf(tm0, fmaxf(s0, s1));
            tm1 = fmaxf(tm1, fmaxf(s2, s3));
        }
        tm0 = fmaxf(tm0, __shfl_xor_sync(0xffffffffu, tm0, 1));
        tm0 = fmaxf(tm0, __shfl_xor_sync(0xffffffffu, tm0, 2));
        tm1 = fmaxf(tm1, __shfl_xor_sync(0xffffffffu, tm1, 1));
        tm1 = fmaxf(tm1, __shfl_xor_sync(0xffffffffu, tm1, 2));

        float mn0 = fmaxf(m0, tm0), mn1 = fmaxf(m1, tm1);
        float cr0 = __expf(m0 - mn0), cr1 = __expf(m1 - mn1);
        l0 *= cr0; l1 *= cr1;
        #pragma unroll
        for (int nb = 0; nb < 8; nb++) {
            oacc[nb][0] *= cr0; oacc[nb][1] *= cr0;
            oacc[nb][2] *= cr1; oacc[nb][3] *= cr1;
        }
        // P = exp(S - m), pack to half2 fragments (acc layout == A-frag layout)
        uint32_t pa01[8], pa23[8];
        #pragma unroll
        for (int nb = 0; nb < 8; nb++) {
            float p0 = __expf(sacc[nb][0] - mn0);
            float p1 = __expf(sacc[nb][1] - mn0);
            float p2 = __expf(sacc[nb][2] - mn1);
            float p3 = __expf(sacc[nb][3] - mn1);
            l0 += p0 + p1; l1 += p2 + p3;
            __half2 h01 = __floats2half2_rn(p0, p1);
            __half2 h23 = __floats2half2_rn(p2, p3);
            pa01[nb] = *(uint32_t*)&h01;
            pa23[nb] = *(uint32_t*)&h23;
        }
        m0 = mn0; m1 = mn1;

        // O += P @ V
        #pragma unroll
        for (int kcc = 0; kcc < 4; kcc++) {
            uint32_t aa[4] = { pa01[2*kcc], pa23[2*kcc], pa01[2*kcc+1], pa23[2*kcc+1] };
            #pragma unroll
            for (int nb = 0; nb < 8; nb++) {
                const __half* p = Vt + (nb * 8 + gid) * KLD + kcc * 16 + 2 * tg;
                uint32_t bb[2] = { *(const uint32_t*)p, *(const uint32_t*)(p + 8) };
                mma_f16(oacc[nb], aa, bb);
            }
        }
    }

    // finalize: reduce l over the quad, normalize, store half
    l0 += __shfl_xor_sync(0xffffffffu, l0, 1);
    l0 += __shfl_xor_sync(0xffffffffu, l0, 2);
    l1 += __shfl_xor_sync(0xffffffffu, l1, 1);
    l1 += __shfl_xor_sync(0xffffffffu, l1, 2);
    float i0 = 1.0f / l0, i1 = 1.0f / l1;

    __half* o0 = out + ((size_t)(b * SS) + rg0) * DIM + h * HDIM + 2 * tg;
    __half* o1 = out + ((size_t)(b * SS) + rg1) * DIM + h * HDIM + 2 * tg;
    #pragma unroll
    for (int nb = 0; nb < 8; nb++) {
        *(__half2*)(o0 + nb * 8) = __floats2half2_rn(oacc[nb][0] * i0, oacc[nb][1] * i0);
        *(__half2*)(o1 + nb * 8) = __floats2half2_rn(oacc[nb][2] * i1, oacc[nb][3] * i1);
    }
}

// ---------------- launch ----------------
extern "C" void kernel_launch(void* const* d_in, const int* in_sizes, int n_in,
                              void* d_out, int out_size) {
    const float* x      = (const float*)d_in[0];
    const float* ln1_w  = (const float*)d_in[1];
    const float* ln1_b  = (const float*)d_in[2];
    const float* qkv_w  = (const float*)d_in[3];
    const float* qkv_b  = (const float*)d_in[4];
    const float* proj_w = (const float*)d_in[5];
    const float* proj_b = (const float*)d_in[6];
    const float* ln2_w  = (const float*)d_in[7];
    const float* ln2_b  = (const float*)d_in[8];
    const float* fc1_w  = (const float*)d_in[9];
    const float* fc1_b  = (const float*)d_in[10];
    const float* fc2_w  = (const float*)d_in[11];
    const float* fc2_b  = (const float*)d_in[12];
    float* out = (float*)d_out;

    __half *xn, *qkv, *attn, *hh, *qkvT, *projT, *fc1T, *fc2T, *vT;
    float *x1;
    cudaGetSymbolAddress((void**)&xn,    h_xn);
    cudaGetSymbolAddress((void**)&qkv,   h_qkv);
    cudaGetSymbolAddress((void**)&attn,  h_attn);
    cudaGetSymbolAddress((void**)&x1,    g_x1);
    cudaGetSymbolAddress((void**)&hh,    h_h);
    cudaGetSymbolAddress((void**)&qkvT,  h_qkvT);
    cudaGetSymbolAddress((void**)&projT, h_projT);
    cudaGetSymbolAddress((void**)&fc1T,  h_fc1T);
    cudaGetSymbolAddress((void**)&fc2T,  h_fc2T);
    cudaGetSymbolAddress((void**)&vT,    h_vT);

    // weight transposes: fp32 [K,N] -> fp16 [N,K]
    transpose_h_kernel<<<dim3(3*DIM/32, DIM/32), 256>>>(qkv_w, qkvT, DIM, 3*DIM);
    transpose_h_kernel<<<dim3(DIM/32, DIM/32), 256>>>(proj_w, projT, DIM, DIM);
    transpose_h_kernel<<<dim3(MLP/32, DIM/32), 256>>>(fc1_w, fc1T, DIM, MLP);
    transpose_h_kernel<<<dim3(DIM/32, MLP/32), 256>>>(fc2_w, fc2T, MLP, DIM);

    // 1. LN1
    ln_kernel<<<TT, 256>>>(x, ln1_w, ln1_b, xn);
    // 2. QKV = xn @ qkv_w + qkv_b  -> half
    gemm_h<0><<<dim3(3*DIM/128, TT/128), 128>>>(TT, 3*DIM, DIM, xn, qkvT, qkv_b, nullptr, qkv);
    // 3. V transpose per head
    vt_kernel<<<dim3(SS/32, HDIM/32, BB*HEADS), 256>>>(qkv, vT);
    // 4. causal attention -> half
    attn_mma<<<dim3(SS/64, BB*HEADS), 128>>>(qkv, vT, attn);
    // 5. x1 = x + attn @ proj_w + proj_b  -> float
    gemm_h<2><<<dim3(DIM/128, TT/128), 128>>>(TT, DIM, DIM, attn, projT, proj_b, x, x1);
    // 6. LN2
    ln_kernel<<<TT, 256>>>(x1, ln2_w, ln2_b, xn);
    // 7. h = gelu(xn @ fc1_w + fc1_b) -> half
    gemm_h<1><<<dim3(MLP/128, TT/128), 128>>>(TT, MLP, DIM, xn, fc1T, fc1_b, nullptr, hh);
    // 8. out = x1 + h @ fc2_w + fc2_b -> float
    gemm_h<2><<<dim3(DIM/128, TT/128), 128>>>(TT, DIM, MLP, hh, fc2T, fc2_b, x1, out);
}

// round 5
// speedup vs baseline: 9.3194x; 1.2745x over previous
#include <cuda_runtime.h>
#include <cuda_fp16.h>
#include <math.h>
#include <stdint.h>

#define DIM   1024
#define HEADS 16
#define HDIM  64
#define MLP   4096
#define BB    4
#define SS    2048
#define TT    (BB*SS)   // 8192 tokens

// ---------------- scratch (device globals; no allocation) ----------------
__device__ __half h_xn[(size_t)TT*DIM];
__device__ __half h_qkv[(size_t)TT*3*DIM];
__device__ __half h_attn[(size_t)TT*DIM];
__device__ float  g_x1[(size_t)TT*DIM];
__device__ __half h_h[(size_t)TT*MLP];
__device__ __half h_qkvT[(size_t)3*DIM*DIM];
__device__ __half h_projT[(size_t)DIM*DIM];
__device__ __half h_fc1T[(size_t)DIM*MLP];
__device__ __half h_fc2T[(size_t)MLP*DIM];
__device__ __half h_vT[(size_t)BB*HEADS*HDIM*SS];

// ---------------- ptx helpers ----------------
__device__ __forceinline__ void mma_f16(float* c, const uint32_t* a, const uint32_t* b) {
    asm volatile(
        "mma.sync.aligned.m16n8k16.row.col.f32.f16.f16.f32 "
        "{%0,%1,%2,%3}, {%4,%5,%6,%7}, {%8,%9}, {%0,%1,%2,%3};"
        : "+f"(c[0]), "+f"(c[1]), "+f"(c[2]), "+f"(c[3])
        : "r"(a[0]), "r"(a[1]), "r"(a[2]), "r"(a[3]), "r"(b[0]), "r"(b[1]));
}

__device__ __forceinline__ void ldmx4(uint32_t& r0, uint32_t& r1, uint32_t& r2, uint32_t& r3,
                                      const __half* p) {
    uint32_t a = (uint32_t)__cvta_generic_to_shared((void*)p);
    asm volatile("ldmatrix.sync.aligned.m8n8.x4.shared.b16 {%0,%1,%2,%3}, [%4];"
                 : "=r"(r0), "=r"(r1), "=r"(r2), "=r"(r3) : "r"(a));
}

__device__ __forceinline__ void cpa16(__half* dst, const __half* src) {
    uint32_t s = (uint32_t)__cvta_generic_to_shared((void*)dst);
    asm volatile("cp.async.cg.shared.global [%0], [%1], 16;" :: "r"(s), "l"(src));
}
#define CP_COMMIT() asm volatile("cp.async.commit_group;" ::: "memory")
#define CP_WAIT1()  asm volatile("cp.async.wait_group 1;" ::: "memory")

// ---------------- LayerNorm: fp32 in -> fp16 out ----------------
__global__ __launch_bounds__(256)
void ln_kernel(const float* __restrict__ x, const float* __restrict__ w,
               const float* __restrict__ b, __half* __restrict__ out) {
    int row = blockIdx.x;
    int tid = threadIdx.x;
    const float4* xr = (const float4*)(x + (size_t)row * DIM);
    float4 v = xr[tid];
    float s  = v.x + v.y + v.z + v.w;
    float ss = v.x*v.x + v.y*v.y + v.z*v.z + v.w*v.w;
    #pragma unroll
    for (int o = 16; o; o >>= 1) {
        s  += __shfl_xor_sync(0xffffffffu, s,  o);
        ss += __shfl_xor_sync(0xffffffffu, ss, o);
    }
    __shared__ float red0[8], red1[8];
    int wid = tid >> 5, lid = tid & 31;
    if (lid == 0) { red0[wid] = s; red1[wid] = ss; }
    __syncthreads();
    float sum = 0.f, sumsq = 0.f;
    #pragma unroll
    for (int i = 0; i < 8; i++) { sum += red0[i]; sumsq += red1[i]; }
    float mu   = sum * (1.0f / DIM);
    float var  = sumsq * (1.0f / DIM) - mu * mu;
    float rstd = rsqrtf(var + 1e-5f);
    float4 wv = ((const float4*)w)[tid];
    float4 bv = ((const float4*)b)[tid];
    __half2* o2 = (__half2*)(out + (size_t)row * DIM);
    o2[tid*2+0] = __floats2half2_rn((v.x - mu)*rstd*wv.x + bv.x,
                                    (v.y - mu)*rstd*wv.y + bv.y);
    o2[tid*2+1] = __floats2half2_rn((v.z - mu)*rstd*wv.z + bv.z,
                                    (v.w - mu)*rstd*wv.w + bv.w);
}

// ---------------- weight transpose [K,N] fp32 -> [N,K] fp16 ----------------
__global__ __launch_bounds__(256)
void transpose_h_kernel(const float* __restrict__ in, __half* __restrict__ out,
                        int K, int N) {
    __shared__ float tile[32][33];
    int bx = blockIdx.x;
    int by = blockIdx.y;
    int tx = threadIdx.x & 31;
    int ty = threadIdx.x >> 5;
    #pragma unroll
    for (int i = 0; i < 32; i += 8)
        tile[ty + i][tx] = in[(size_t)(by * 32 + ty + i) * N + bx * 32 + tx];
    __syncthreads();
    #pragma unroll
    for (int i = 0; i < 32; i += 8)
        out[(size_t)(bx * 32 + ty + i) * K + by * 32 + tx] = __float2half_rn(tile[tx][ty + i]);
}

// ---------------- V transpose ----------------
__global__ __launch_bounds__(256)
void vt_kernel(const __half* __restrict__ qkv, __half* __restrict__ vT) {
    __shared__ __half t[32][33];
    int s0 = blockIdx.x * 32;
    int d0 = blockIdx.y * 32;
    int bh = blockIdx.z;
    int b = bh >> 4, h = bh & 15;
    int tx = threadIdx.x & 31, ty = threadIdx.x >> 5;
    #pragma unroll
    for (int i = 0; i < 32; i += 8)
        t[ty + i][tx] = qkv[((size_t)(b*SS) + s0 + ty + i) * (3*DIM) + 2*DIM + h*HDIM + d0 + tx];
    __syncthreads();
    #pragma unroll
    for (int i = 0; i < 32; i += 8)
        vT[((size_t)bh * HDIM + d0 + ty + i) * SS + s0 + tx] = t[tx][ty + i];
}

// ---------------- fp16 mma GEMM, cp.async 3-stage + ldmatrix ----------------
// EPI: 0 = +bias -> half ; 1 = +bias, GELU -> half ; 2 = +bias, +residual -> float
// BM=BN=128, BK=32, 128 threads (4 warps, warp tile 64x64).
#define GLDA 40
#define STG_H (2 * 128 * GLDA)   // halves per stage (A then B)

template <int EPI>
__global__ __launch_bounds__(128, 2)
void gemm_h(int M, int N, int K,
            const __half* __restrict__ A, const __half* __restrict__ Bt,
            const float* __restrict__ bias, const float* __restrict__ R,
            void* __restrict__ Cout) {
    __shared__ __half sh[3 * STG_H];

    int tid = threadIdx.x;
    int wid = tid >> 5, lane = tid & 31;
    int gid = lane >> 2, tg = lane & 3;
    int wm = wid & 1, wn = wid >> 1;
    int bx = blockIdx.x, by = blockIdx.y;

    const __half* Ab = A  + (size_t)(by * 128) * K;
    const __half* Bb = Bt + (size_t)(bx * 128) * K;

    int ldr = tid >> 2;            // 0..31 row base (idx/4 pattern below)
    (void)ldr;

    float acc[4][8][4];
    #pragma unroll
    for (int i = 0; i < 4; i++)
        #pragma unroll
        for (int j = 0; j < 8; j++)
            #pragma unroll
            for (int c = 0; c < 4; c++) acc[i][j][c] = 0.f;

    int NC = K / 32;

    // issue stage s loads (A and B tiles, 16B each, 4 per thread per operand)
    auto issue = [&](int s, int kb) {
        __half* sa = sh + (s % 3) * STG_H;
        __half* sb = sa + 128 * GLDA;
        #pragma unroll
        for (int it = 0; it < 4; it++) {
            int idx = it * 128 + tid;
            int r = idx >> 2, c8 = (idx & 3) * 8;
            cpa16(sa + r * GLDA + c8, Ab + (size_t)r * K + kb + c8);
            cpa16(sb + r * GLDA + c8, Bb + (size_t)r * K + kb + c8);
        }
    };

    issue(0, 0);  CP_COMMIT();
    if (NC > 1) { issue(1, 32); }
    CP_COMMIT();

    for (int kc = 0; kc < NC; kc++) {
        CP_WAIT1();
        __syncthreads();
        const __half* Ac = sh + (kc % 3) * STG_H;
        const __half* Bc = Ac + 128 * GLDA;

        #pragma unroll
        for (int kk = 0; kk < 32; kk += 16) {
            uint32_t af[4][4];
            #pragma unroll
            for (int mf = 0; mf < 4; mf++) {
                const __half* p = Ac + (wm * 64 + mf * 16 + (lane & 15)) * GLDA
                                  + kk + (lane >> 4) * 8;
                ldmx4(af[mf][0], af[mf][1], af[mf][2], af[mf][3], p);
            }
            uint32_t bf[8][2];
            #pragma unroll
            for (int pj = 0; pj < 4; pj++) {
                const __half* p = Bc + (wn * 64 + (pj * 2 + (lane >> 4)) * 8 + (lane & 7)) * GLDA
                                  + kk + ((lane >> 3) & 1) * 8;
                ldmx4(bf[2*pj][0], bf[2*pj][1], bf[2*pj+1][0], bf[2*pj+1][1], p);
            }
            #pragma unroll
            for (int mf = 0; mf < 4; mf++)
                #pragma unroll
                for (int nb = 0; nb < 8; nb++)
                    mma_f16(acc[mf][nb], af[mf], bf[nb]);
        }
        __syncthreads();
        if (kc + 2 < NC) { issue(kc + 2, (kc + 2) * 32); }
        CP_COMMIT();
    }

    // epilogue
    int colW = bx * 128 + wn * 64;
    #pragma unroll
    for (int mf = 0; mf < 4; mf++) {
        #pragma unroll
        for (int r2 = 0; r2 < 2; r2++) {
            int row = by * 128 + wm * 64 + mf * 16 + gid + r2 * 8;
            #pragma unroll
            for (int nb = 0; nb < 8; nb++) {
                int gcol = colW + nb * 8 + 2 * tg;
                float t0 = acc[mf][nb][r2 * 2 + 0] + bias[gcol];
                float t1 = acc[mf][nb][r2 * 2 + 1] + bias[gcol + 1];
                if (EPI == 1) {
                    t0 = 0.5f * t0 * (1.0f + erff(t0 * 0.70710678118654752f));
                    t1 = 0.5f * t1 * (1.0f + erff(t1 * 0.70710678118654752f));
                }
                if (EPI == 2) {
                    float2 rv = *(const float2*)(R + (size_t)row * N + gcol);
                    t0 += rv.x; t1 += rv.y;
                    *(float2*)((float*)Cout + (size_t)row * N + gcol) = make_float2(t0, t1);
                } else {
                    *(__half2*)((__half*)Cout + (size_t)row * N + gcol) = __floats2half2_rn(t0, t1);
                }
            }
        }
    }
}

// ---------------- causal flash attention with fp16 mma + ldmatrix ----------------
#define KLD 72

__global__ __launch_bounds__(128)
void attn_mma(const __half* __restrict__ qkv, const __half* __restrict__ vT,
              __half* __restrict__ out) {
    int qt = blockIdx.x, bh = blockIdx.y;
    int b = bh >> 4, h = bh & 15;
    int tid = threadIdx.x;
    int wid = tid >> 5, lane = tid & 31;
    int gid = lane >> 2, tg = lane & 3;
    int q0 = qt * 64;

    __shared__ __half Ks[64 * KLD];
    __shared__ __half Vt[64 * KLD];

    uint32_t qa[4][4];
    {
        const __half* Q0 = qkv + ((size_t)(b * SS) + q0 + wid * 16 + gid) * (3 * DIM) + h * HDIM + 2 * tg;
        const __half* Q1 = Q0 + (size_t)8 * (3 * DIM);
        #pragma unroll
        for (int kcc = 0; kcc < 4; kcc++) {
            qa[kcc][0] = *(const uint32_t*)(Q0 + kcc * 16);
            qa[kcc][1] = *(const uint32_t*)(Q1 + kcc * 16);
            qa[kcc][2] = *(const uint32_t*)(Q0 + kcc * 16 + 8);
            qa[kcc][3] = *(const uint32_t*)(Q1 + kcc * 16 + 8);
        }
    }

    float oacc[8][4];
    #pragma unroll
    for (int nb = 0; nb < 8; nb++)
        #pragma unroll
        for (int c = 0; c < 4; c++) oacc[nb][c] = 0.f;
    float m0 = -1e30f, m1 = -1e30f, l0 = 0.f, l1 = 0.f;
    int rg0 = q0 + wid * 16 + gid;
    int rg1 = rg0 + 8;

    // ldmatrix lane addressing (shared by K and V tiles)
    int lm_row = ((lane >> 4)) * 8 + (lane & 7);    // within a 16-row pair block
    int lm_koff = ((lane >> 3) & 1) * 8;

    for (int jt = 0; jt <= qt; jt++) {
        __syncthreads();
        #pragma unroll
        for (int it = 0; it < 4; it++) {
            int idx = it * 128 + tid;
            int r = idx >> 3, c8 = (idx & 7) * 8;
            *(int4*)(Ks + r * KLD + c8) =
                *(const int4*)(qkv + ((size_t)(b * SS) + jt * 64 + r) * (3 * DIM) + DIM + h * HDIM + c8);
            *(int4*)(Vt + r * KLD + c8) =
                *(const int4*)(vT + ((size_t)bh * HDIM + r) * SS + jt * 64 + c8);
        }
        __syncthreads();

        // S = Q @ K^T
        float sacc[8][4];
        #pragma unroll
        for (int nb = 0; nb < 8; nb++)
            #pragma unroll
            for (int c = 0; c < 4; c++) sacc[nb][c] = 0.f;
        #pragma unroll
        for (int kcc = 0; kcc < 4; kcc++) {
            uint32_t bf[8][2];
            #pragma unroll
            for (int pj = 0; pj < 4; pj++) {
                const __half* p = Ks + (pj * 16 + lm_row) * KLD + kcc * 16 + lm_koff;
                ldmx4(bf[2*pj][0], bf[2*pj][1], bf[2*pj+1][0], bf[2*pj+1][1], p);
            }
            #pragma unroll
            for (int nb = 0; nb < 8; nb++)
                mma_f16(sacc[nb], qa[kcc], bf[nb]);
        }

        const float sc = 0.125f;
        float tm0 = -1e30f, tm1 = -1e30f;
        #pragma unroll
        for (int nb = 0; nb < 8; nb++) {
            int col = jt * 64 + nb * 8 + 2 * tg;
            float s0 = sacc[nb][0] * sc, s1 = sacc[nb][1] * sc;
            float s2 = sacc[nb][2] * sc, s3 = sacc[nb][3] * sc;
            if (jt == qt) {
                if (col     > rg0) s0 = -1e30f;
                if (col + 1 > rg0) s1 = -1e30f;
                if (col     > rg1) s2 = -1e30f;
                if (col + 1 > rg1) s3 = -1e30f;
            }
            sacc[nb][0] = s0; sacc[nb][1] = s1; sacc[nb][2] = s2; sacc[nb][3] = s3;
            tm0 = fmaxf(tm0, fmaxf(s0, s1));
            tm1 = fmaxf(tm1, fmaxf(s2, s3));
        }
        tm0 = fmaxf(tm0, __shfl_xor_sync(0xffffffffu, tm0, 1));
        tm0 = fmaxf(tm0, __shfl_xor_sync(0xffffffffu, tm0, 2));
        tm1 = fmaxf(tm1, __shfl_xor_sync(0xffffffffu, tm1, 1));
        tm1 = fmaxf(tm1, __shfl_xor_sync(0xffffffffu, tm1, 2));

        float mn0 = fmaxf(m0, tm0), mn1 = fmaxf(m1, tm1);
        float cr0 = __expf(m0 - mn0), cr1 = __expf(m1 - mn1);
        l0 *= cr0; l1 *= cr1;
        #pragma unroll
        for (int nb = 0; nb < 8; nb++) {
            oacc[nb][0] *= cr0; oacc[nb][1] *= cr0;
            oacc[nb][2] *= cr1; oacc[nb][3] *= cr1;
        }
        uint32_t pa01[8], pa23[8];
        #pragma unroll
        for (int nb = 0; nb < 8; nb++) {
            float p0 = __expf(sacc[nb][0] - mn0);
            float p1 = __expf(sacc[nb][1] - mn0);
            float p2 = __expf(sacc[nb][2] - mn1);
            float p3 = __expf(sacc[nb][3] - mn1);
            l0 += p0 + p1; l1 += p2 + p3;
            __half2 h01 = __floats2half2_rn(p0, p1);
            __half2 h23 = __floats2half2_rn(p2, p3);
            pa01[nb] = *(uint32_t*)&h01;
            pa23[nb] = *(uint32_t*)&h23;
        }
        m0 = mn0; m1 = mn1;

        // O += P @ V
        #pragma unroll
        for (int kcc = 0; kcc < 4; kcc++) {
            uint32_t aa[4] = { pa01[2*kcc], pa23[2*kcc], pa01[2*kcc+1], pa23[2*kcc+1] };
            uint32_t bf[8][2];
            #pragma unroll
            for (int pj = 0; pj < 4; pj++) {
                const __half* p = Vt + (pj * 16 + lm_row) * KLD + kcc * 16 + lm_koff;
                ldmx4(bf[2*pj][0], bf[2*pj][1], bf[2*pj+1][0], bf[2*pj+1][1], p);
            }
            #pragma unroll
            for (int nb = 0; nb < 8; nb++)
                mma_f16(oacc[nb], aa, bf[nb]);
        }
    }

    l0 += __shfl_xor_sync(0xffffffffu, l0, 1);
    l0 += __shfl_xor_sync(0xffffffffu, l0, 2);
    l1 += __shfl_xor_sync(0xffffffffu, l1, 1);
    l1 += __shfl_xor_sync(0xffffffffu, l1, 2);
    float i0 = 1.0f / l0, i1 = 1.0f / l1;

    __half* o0 = out + ((size_t)(b * SS) + rg0) * DIM + h * HDIM + 2 * tg;
    __half* o1 = out + ((size_t)(b * SS) + rg1) * DIM + h * HDIM + 2 * tg;
    #pragma unroll
    for (int nb = 0; nb < 8; nb++) {
        *(__half2*)(o0 + nb * 8) = __floats2half2_rn(oacc[nb][0] * i0, oacc[nb][1] * i0);
        *(__half2*)(o1 + nb * 8) = __floats2half2_rn(oacc[nb][2] * i1, oacc[nb][3] * i1);
    }
}

// ---------------- launch ----------------
extern "C" void kernel_launch(void* const* d_in, const int* in_sizes, int n_in,
                              void* d_out, int out_size) {
    const float* x      = (const float*)d_in[0];
    const float* ln1_w  = (const float*)d_in[1];
    const float* ln1_b  = (const float*)d_in[2];
    const float* qkv_w  = (const float*)d_in[3];
    const float* qkv_b  = (const float*)d_in[4];
    const float* proj_w = (const float*)d_in[5];
    const float* proj_b = (const float*)d_in[6];
    const float* ln2_w  = (const float*)d_in[7];
    const float* ln2_b  = (const float*)d_in[8];
    const float* fc1_w  = (const float*)d_in[9];
    const float* fc1_b  = (const float*)d_in[10];
    const float* fc2_w  = (const float*)d_in[11];
    const float* fc2_b  = (const float*)d_in[12];
    float* out = (float*)d_out;

    __half *xn, *qkv, *attn, *hh, *qkvT, *projT, *fc1T, *fc2T, *vT;
    float *x1;
    cudaGetSymbolAddress((void**)&xn,    h_xn);
    cudaGetSymbolAddress((void**)&qkv,   h_qkv);
    cudaGetSymbolAddress((void**)&attn,  h_attn);
    cudaGetSymbolAddress((void**)&x1,    g_x1);
    cudaGetSymbolAddress((void**)&hh,    h_h);
    cudaGetSymbolAddress((void**)&qkvT,  h_qkvT);
    cudaGetSymbolAddress((void**)&projT, h_projT);
    cudaGetSymbolAddress((void**)&fc1T,  h_fc1T);
    cudaGetSymbolAddress((void**)&fc2T,  h_fc2T);
    cudaGetSymbolAddress((void**)&vT,    h_vT);

    transpose_h_kernel<<<dim3(3*DIM/32, DIM/32), 256>>>(qkv_w, qkvT, DIM, 3*DIM);
    transpose_h_kernel<<<dim3(DIM/32, DIM/32), 256>>>(proj_w, projT, DIM, DIM);
    transpose_h_kernel<<<dim3(MLP/32, DIM/32), 256>>>(fc1_w, fc1T, DIM, MLP);
    transpose_h_kernel<<<dim3(DIM/32, MLP/32), 256>>>(fc2_w, fc2T, MLP, DIM);

    ln_kernel<<<TT, 256>>>(x, ln1_w, ln1_b, xn);
    gemm_h<0><<<dim3(3*DIM/128, TT/128), 128>>>(TT, 3*DIM, DIM, xn, qkvT, qkv_b, nullptr, qkv);
    vt_kernel<<<dim3(SS/32, HDIM/32, BB*HEADS), 256>>>(qkv, vT);
    attn_mma<<<dim3(SS/64, BB*HEADS), 128>>>(qkv, vT, attn);
    gemm_h<2><<<dim3(DIM/128, TT/128), 128>>>(TT, DIM, DIM, attn, projT, proj_b, x, x1);
    ln_kernel<<<TT, 256>>>(x1, ln2_w, ln2_b, xn);
    gemm_h<1><<<dim3(MLP/128, TT/128), 128>>>(TT, MLP, DIM, xn, fc1T, fc1_b, nullptr, hh);
    gemm_h<2><<<dim3(DIM/128, TT/128), 128>>>(TT, DIM, MLP, hh, fc2T, fc2_b, x1, out);
}

// round 6
// speedup vs baseline: 9.8746x; 1.0596x over previous
#include <cuda_runtime.h>
#include <cuda_fp16.h>
#include <math.h>
#include <stdint.h>

#define DIM   1024
#define HEADS 16
#define HDIM  64
#define MLP   4096
#define BB    4
#define SS    2048
#define TT    (BB*SS)   // 8192 tokens

// ---------------- scratch (device globals; no allocation) ----------------
__device__ __half h_xn[(size_t)TT*DIM];
__device__ __half h_qkv[(size_t)TT*3*DIM];
__device__ __half h_attn[(size_t)TT*DIM];
__device__ float  g_x1[(size_t)TT*DIM];
__device__ __half h_h[(size_t)TT*MLP];
__device__ __half h_qkvT[(size_t)3*DIM*DIM];
__device__ __half h_projT[(size_t)DIM*DIM];
__device__ __half h_fc1T[(size_t)DIM*MLP];
__device__ __half h_fc2T[(size_t)MLP*DIM];
__device__ __half h_vT[(size_t)BB*HEADS*HDIM*SS];

// ---------------- ptx helpers ----------------
__device__ __forceinline__ void mma_f16(float* c, const uint32_t* a, const uint32_t* b) {
    asm volatile(
        "mma.sync.aligned.m16n8k16.row.col.f32.f16.f16.f32 "
        "{%0,%1,%2,%3}, {%4,%5,%6,%7}, {%8,%9}, {%0,%1,%2,%3};"
        : "+f"(c[0]), "+f"(c[1]), "+f"(c[2]), "+f"(c[3])
        : "r"(a[0]), "r"(a[1]), "r"(a[2]), "r"(a[3]), "r"(b[0]), "r"(b[1]));
}

__device__ __forceinline__ void ldmx4(uint32_t& r0, uint32_t& r1, uint32_t& r2, uint32_t& r3,
                                      const __half* p) {
    uint32_t a = (uint32_t)__cvta_generic_to_shared((void*)p);
    asm volatile("ldmatrix.sync.aligned.m8n8.x4.shared.b16 {%0,%1,%2,%3}, [%4];"
                 : "=r"(r0), "=r"(r1), "=r"(r2), "=r"(r3) : "r"(a));
}

__device__ __forceinline__ void cpa16(__half* dst, const __half* src) {
    uint32_t s = (uint32_t)__cvta_generic_to_shared((void*)dst);
    asm volatile("cp.async.cg.shared.global [%0], [%1], 16;" :: "r"(s), "l"(src));
}
#define CP_COMMIT() asm volatile("cp.async.commit_group;" ::: "memory")
#define CP_WAIT2()  asm volatile("cp.async.wait_group 2;" ::: "memory")
#define CP_WAIT1()  asm volatile("cp.async.wait_group 1;" ::: "memory")

// ---------------- LayerNorm: fp32 in -> fp16 out ----------------
__global__ __launch_bounds__(256)
void ln_kernel(const float* __restrict__ x, const float* __restrict__ w,
               const float* __restrict__ b, __half* __restrict__ out) {
    int row = blockIdx.x;
    int tid = threadIdx.x;
    const float4* xr = (const float4*)(x + (size_t)row * DIM);
    float4 v = xr[tid];
    float s  = v.x + v.y + v.z + v.w;
    float ss = v.x*v.x + v.y*v.y + v.z*v.z + v.w*v.w;
    #pragma unroll
    for (int o = 16; o; o >>= 1) {
        s  += __shfl_xor_sync(0xffffffffu, s,  o);
        ss += __shfl_xor_sync(0xffffffffu, ss, o);
    }
    __shared__ float red0[8], red1[8];
    int wid = tid >> 5, lid = tid & 31;
    if (lid == 0) { red0[wid] = s; red1[wid] = ss; }
    __syncthreads();
    float sum = 0.f, sumsq = 0.f;
    #pragma unroll
    for (int i = 0; i < 8; i++) { sum += red0[i]; sumsq += red1[i]; }
    float mu   = sum * (1.0f / DIM);
    float var  = sumsq * (1.0f / DIM) - mu * mu;
    float rstd = rsqrtf(var + 1e-5f);
    float4 wv = ((const float4*)w)[tid];
    float4 bv = ((const float4*)b)[tid];
    __half2* o2 = (__half2*)(out + (size_t)row * DIM);
    o2[tid*2+0] = __floats2half2_rn((v.x - mu)*rstd*wv.x + bv.x,
                                    (v.y - mu)*rstd*wv.y + bv.y);
    o2[tid*2+1] = __floats2half2_rn((v.z - mu)*rstd*wv.z + bv.z,
                                    (v.w - mu)*rstd*wv.w + bv.w);
}

// ---------------- weight transpose [K,N] fp32 -> [N,K] fp16 ----------------
__global__ __launch_bounds__(256)
void transpose_h_kernel(const float* __restrict__ in, __half* __restrict__ out,
                        int K, int N) {
    __shared__ float tile[32][33];
    int bx = blockIdx.x;
    int by = blockIdx.y;
    int tx = threadIdx.x & 31;
    int ty = threadIdx.x >> 5;
    #pragma unroll
    for (int i = 0; i < 32; i += 8)
        tile[ty + i][tx] = in[(size_t)(by * 32 + ty + i) * N + bx * 32 + tx];
    __syncthreads();
    #pragma unroll
    for (int i = 0; i < 32; i += 8)
        out[(size_t)(bx * 32 + ty + i) * K + by * 32 + tx] = __float2half_rn(tile[tx][ty + i]);
}

// ---------------- V transpose ----------------
__global__ __launch_bounds__(256)
void vt_kernel(const __half* __restrict__ qkv, __half* __restrict__ vT) {
    __shared__ __half t[32][33];
    int s0 = blockIdx.x * 32;
    int d0 = blockIdx.y * 32;
    int bh = blockIdx.z;
    int b = bh >> 4, h = bh & 15;
    int tx = threadIdx.x & 31, ty = threadIdx.x >> 5;
    #pragma unroll
    for (int i = 0; i < 32; i += 8)
        t[ty + i][tx] = qkv[((size_t)(b*SS) + s0 + ty + i) * (3*DIM) + 2*DIM + h*HDIM + d0 + tx];
    __syncthreads();
    #pragma unroll
    for (int i = 0; i < 32; i += 8)
        vT[((size_t)bh * HDIM + d0 + ty + i) * SS + s0 + tx] = t[tx][ty + i];
}

// ---------------- fp16 mma GEMM, 4-stage cp.async + ldmatrix, 1 sync/chunk ----------------
// EPI: 0 = +bias -> half ; 1 = +bias, GELU -> half ; 2 = +bias, +residual -> float
#define GLDA 40
#define STG_H (2 * 128 * GLDA)   // halves per stage (A then B)

template <int EPI>
__global__ __launch_bounds__(128, 2)
void gemm_h(int M, int N, int K,
            const __half* __restrict__ A, const __half* __restrict__ Bt,
            const float* __restrict__ bias, const float* __restrict__ R,
            void* __restrict__ Cout) {
    __shared__ __half sh[4 * STG_H];

    int tid = threadIdx.x;
    int wid = tid >> 5, lane = tid & 31;
    int gid = lane >> 2, tg = lane & 3;
    int wm = wid & 1, wn = wid >> 1;
    int bx = blockIdx.x, by = blockIdx.y;

    const __half* Ab = A  + (size_t)(by * 128) * K;
    const __half* Bb = Bt + (size_t)(bx * 128) * K;

    float acc[4][8][4];
    #pragma unroll
    for (int i = 0; i < 4; i++)
        #pragma unroll
        for (int j = 0; j < 8; j++)
            #pragma unroll
            for (int c = 0; c < 4; c++) acc[i][j][c] = 0.f;

    int NC = K / 32;

    auto issue = [&](int s) {
        if (s < NC) {
            __half* sa = sh + (s & 3) * STG_H;
            __half* sb = sa + 128 * GLDA;
            int kb = s * 32;
            #pragma unroll
            for (int it = 0; it < 4; it++) {
                int idx = it * 128 + tid;
                int r = idx >> 2, c8 = (idx & 3) * 8;
                cpa16(sa + r * GLDA + c8, Ab + (size_t)r * K + kb + c8);
                cpa16(sb + r * GLDA + c8, Bb + (size_t)r * K + kb + c8);
            }
        }
        CP_COMMIT();
    };

    issue(0); issue(1); issue(2);

    for (int kc = 0; kc < NC; kc++) {
        CP_WAIT2();
        __syncthreads();
        issue(kc + 3);   // refills buffer (kc-1)&3: all warps past compute(kc-1)

        const __half* Ac = sh + (kc & 3) * STG_H;
        const __half* Bc = Ac + 128 * GLDA;

        #pragma unroll
        for (int kk = 0; kk < 32; kk += 16) {
            uint32_t af[4][4];
            #pragma unroll
            for (int mf = 0; mf < 4; mf++) {
                const __half* p = Ac + (wm * 64 + mf * 16 + (lane & 15)) * GLDA
                                  + kk + (lane >> 4) * 8;
                ldmx4(af[mf][0], af[mf][1], af[mf][2], af[mf][3], p);
            }
            uint32_t bf[8][2];
            #pragma unroll
            for (int pj = 0; pj < 4; pj++) {
                const __half* p = Bc + (wn * 64 + (pj * 2 + (lane >> 4)) * 8 + (lane & 7)) * GLDA
                                  + kk + ((lane >> 3) & 1) * 8;
                ldmx4(bf[2*pj][0], bf[2*pj][1], bf[2*pj+1][0], bf[2*pj+1][1], p);
            }
            #pragma unroll
            for (int mf = 0; mf < 4; mf++)
                #pragma unroll
                for (int nb = 0; nb < 8; nb++)
                    mma_f16(acc[mf][nb], af[mf], bf[nb]);
        }
    }

    // epilogue
    int colW = bx * 128 + wn * 64;
    #pragma unroll
    for (int mf = 0; mf < 4; mf++) {
        #pragma unroll
        for (int r2 = 0; r2 < 2; r2++) {
            int row = by * 128 + wm * 64 + mf * 16 + gid + r2 * 8;
            #pragma unroll
            for (int nb = 0; nb < 8; nb++) {
                int gcol = colW + nb * 8 + 2 * tg;
                float t0 = acc[mf][nb][r2 * 2 + 0] + bias[gcol];
                float t1 = acc[mf][nb][r2 * 2 + 1] + bias[gcol + 1];
                if (EPI == 1) {
                    t0 = 0.5f * t0 * (1.0f + erff(t0 * 0.70710678118654752f));
                    t1 = 0.5f * t1 * (1.0f + erff(t1 * 0.70710678118654752f));
                }
                if (EPI == 2) {
                    float2 rv = *(const float2*)(R + (size_t)row * N + gcol);
                    t0 += rv.x; t1 += rv.y;
                    *(float2*)((float*)Cout + (size_t)row * N + gcol) = make_float2(t0, t1);
                } else {
                    *(__half2*)((__half*)Cout + (size_t)row * N + gcol) = __floats2half2_rn(t0, t1);
                }
            }
        }
    }
}

// ---------------- causal flash attention, cp.async triple-buffer + ldmatrix ----------------
#define KLD 72
#define ATILE (64 * KLD)

__global__ __launch_bounds__(128)
void attn_mma(const __half* __restrict__ qkv, const __half* __restrict__ vT,
              __half* __restrict__ out) {
    int qt = blockIdx.x, bh = blockIdx.y;
    int b = bh >> 4, h = bh & 15;
    int tid = threadIdx.x;
    int wid = tid >> 5, lane = tid & 31;
    int gid = lane >> 2, tg = lane & 3;
    int q0 = qt * 64;

    __shared__ __half Ks3[3 * ATILE];
    __shared__ __half Vt3[3 * ATILE];

    auto issueA = [&](int s) {
        if (s <= qt) {
            __half* ka = Ks3 + (s % 3) * ATILE;
            __half* va = Vt3 + (s % 3) * ATILE;
            #pragma unroll
            for (int it = 0; it < 4; it++) {
                int idx = it * 128 + tid;
                int r = idx >> 3, c8 = (idx & 7) * 8;
                cpa16(ka + r * KLD + c8,
                      qkv + ((size_t)(b * SS) + s * 64 + r) * (3 * DIM) + DIM + h * HDIM + c8);
                cpa16(va + r * KLD + c8,
                      vT + ((size_t)bh * HDIM + r) * SS + s * 64 + c8);
            }
        }
        CP_COMMIT();
    };

    uint32_t qa[4][4];
    {
        const __half* Q0 = qkv + ((size_t)(b * SS) + q0 + wid * 16 + gid) * (3 * DIM) + h * HDIM + 2 * tg;
        const __half* Q1 = Q0 + (size_t)8 * (3 * DIM);
        #pragma unroll
        for (int kcc = 0; kcc < 4; kcc++) {
            qa[kcc][0] = *(const uint32_t*)(Q0 + kcc * 16);
            qa[kcc][1] = *(const uint32_t*)(Q1 + kcc * 16);
            qa[kcc][2] = *(const uint32_t*)(Q0 + kcc * 16 + 8);
            qa[kcc][3] = *(const uint32_t*)(Q1 + kcc * 16 + 8);
        }
    }

    issueA(0); issueA(1);

    float oacc[8][4];
    #pragma unroll
    for (int nb = 0; nb < 8; nb++)
        #pragma unroll
        for (int c = 0; c < 4; c++) oacc[nb][c] = 0.f;
    float m0 = -1e30f, m1 = -1e30f, l0 = 0.f, l1 = 0.f;
    int rg0 = q0 + wid * 16 + gid;
    int rg1 = rg0 + 8;

    int lm_row = ((lane >> 4)) * 8 + (lane & 7);
    int lm_koff = ((lane >> 3) & 1) * 8;

    for (int jt = 0; jt <= qt; jt++) {
        CP_WAIT1();            // group jt complete (all but most-recent group)
        __syncthreads();
        issueA(jt + 2);        // refills buffer (jt-1)%3: all warps past compute(jt-1)

        const __half* Kc = Ks3 + (jt % 3) * ATILE;
        const __half* Vc = Vt3 + (jt % 3) * ATILE;

        // S = Q @ K^T
        float sacc[8][4];
        #pragma unroll
        for (int nb = 0; nb < 8; nb++)
            #pragma unroll
            for (int c = 0; c < 4; c++) sacc[nb][c] = 0.f;
        #pragma unroll
        for (int kcc = 0; kcc < 4; kcc++) {
            uint32_t bf[8][2];
            #pragma unroll
            for (int pj = 0; pj < 4; pj++) {
                const __half* p = Kc + (pj * 16 + lm_row) * KLD + kcc * 16 + lm_koff;
                ldmx4(bf[2*pj][0], bf[2*pj][1], bf[2*pj+1][0], bf[2*pj+1][1], p);
            }
            #pragma unroll
            for (int nb = 0; nb < 8; nb++)
                mma_f16(sacc[nb], qa[kcc], bf[nb]);
        }

        const float sc = 0.125f;
        float tm0 = -1e30f, tm1 = -1e30f;
        #pragma unroll
        for (int nb = 0; nb < 8; nb++) {
            int col = jt * 64 + nb * 8 + 2 * tg;
            float s0 = sacc[nb][0] * sc, s1 = sacc[nb][1] * sc;
            float s2 = sacc[nb][2] * sc, s3 = sacc[nb][3] * sc;
            if (jt == qt) {
                if (col     > rg0) s0 = -1e30f;
                if (col + 1 > rg0) s1 = -1e30f;
                if (col     > rg1) s2 = -1e30f;
                if (col + 1 > rg1) s3 = -1e30f;
            }
            sacc[nb][0] = s0; sacc[nb][1] = s1; sacc[nb][2] = s2; sacc[nb][3] = s3;
            tm0 = fmaxf(tm0, fmaxf(s0, s1));
            tm1 = fmaxf(tm1, fmaxf(s2, s3));
        }
        tm0 = fmaxf(tm0, __shfl_xor_sync(0xffffffffu, tm0, 1));
        tm0 = fmaxf(tm0, __shfl_xor_sync(0xffffffffu, tm0, 2));
        tm1 = fmaxf(tm1, __shfl_xor_sync(0xffffffffu, tm1, 1));
        tm1 = fmaxf(tm1, __shfl_xor_sync(0xffffffffu, tm1, 2));

        float mn0 = fmaxf(m0, tm0), mn1 = fmaxf(m1, tm1);
        float cr0 = __expf(m0 - mn0), cr1 = __expf(m1 - mn1);
        l0 *= cr0; l1 *= cr1;
        #pragma unroll
        for (int nb = 0; nb < 8; nb++) {
            oacc[nb][0] *= cr0; oacc[nb][1] *= cr0;
            oacc[nb][2] *= cr1; oacc[nb][3] *= cr1;
        }
        uint32_t pa01[8], pa23[8];
        #pragma unroll
        for (int nb = 0; nb < 8; nb++) {
            float p0 = __expf(sacc[nb][0] - mn0);
            float p1 = __expf(sacc[nb][1] - mn0);
            float p2 = __expf(sacc[nb][2] - mn1);
            float p3 = __expf(sacc[nb][3] - mn1);
            l0 += p0 + p1; l1 += p2 + p3;
            __half2 h01 = __floats2half2_rn(p0, p1);
            __half2 h23 = __floats2half2_rn(p2, p3);
            pa01[nb] = *(uint32_t*)&h01;
            pa23[nb] = *(uint32_t*)&h23;
        }
        m0 = mn0; m1 = mn1;

        // O += P @ V
        #pragma unroll
        for (int kcc = 0; kcc < 4; kcc++) {
            uint32_t aa[4] = { pa01[2*kcc], pa23[2*kcc], pa01[2*kcc+1], pa23[2*kcc+1] };
            uint32_t bf[8][2];
            #pragma unroll
            for (int pj = 0; pj < 4; pj++) {
                const __half* p = Vc + (pj * 16 + lm_row) * KLD + kcc * 16 + lm_koff;
                ldmx4(bf[2*pj][0], bf[2*pj][1], bf[2*pj+1][0], bf[2*pj+1][1], p);
            }
            #pragma unroll
            for (int nb = 0; nb < 8; nb++)
                mma_f16(oacc[nb], aa, bf[nb]);
        }
    }

    l0 += __shfl_xor_sync(0xffffffffu, l0, 1);
    l0 += __shfl_xor_sync(0xffffffffu, l0, 2);
    l1 += __shfl_xor_sync(0xffffffffu, l1, 1);
    l1 += __shfl_xor_sync(0xffffffffu, l1, 2);
    float i0 = 1.0f / l0, i1 = 1.0f / l1;

    __half* o0 = out + ((size_t)(b * SS) + rg0) * DIM + h * HDIM + 2 * tg;
    __half* o1 = out + ((size_t)(b * SS) + rg1) * DIM + h * HDIM + 2 * tg;
    #pragma unroll
    for (int nb = 0; nb < 8; nb++) {
        *(__half2*)(o0 + nb * 8) = __floats2half2_rn(oacc[nb][0] * i0, oacc[nb][1] * i0);
        *(__half2*)(o1 + nb * 8) = __floats2half2_rn(oacc[nb][2] * i1, oacc[nb][3] * i1);
    }
}

// ---------------- launch ----------------
extern "C" void kernel_launch(void* const* d_in, const int* in_sizes, int n_in,
                              void* d_out, int out_size) {
    const float* x      = (const float*)d_in[0];
    const float* ln1_w  = (const float*)d_in[1];
    const float* ln1_b  = (const float*)d_in[2];
    const float* qkv_w  = (const float*)d_in[3];
    const float* qkv_b  = (const float*)d_in[4];
    const float* proj_w = (const float*)d_in[5];
    const float* proj_b = (const float*)d_in[6];
    const float* ln2_w  = (const float*)d_in[7];
    const float* ln2_b  = (const float*)d_in[8];
    const float* fc1_w  = (const float*)d_in[9];
    const float* fc1_b  = (const float*)d_in[10];
    const float* fc2_w  = (const float*)d_in[11];
    const float* fc2_b  = (const float*)d_in[12];
    float* out = (float*)d_out;

    __half *xn, *qkv, *attn, *hh, *qkvT, *projT, *fc1T, *fc2T, *vT;
    float *x1;
    cudaGetSymbolAddress((void**)&xn,    h_xn);
    cudaGetSymbolAddress((void**)&qkv,   h_qkv);
    cudaGetSymbolAddress((void**)&attn,  h_attn);
    cudaGetSymbolAddress((void**)&x1,    g_x1);
    cudaGetSymbolAddress((void**)&hh,    h_h);
    cudaGetSymbolAddress((void**)&qkvT,  h_qkvT);
    cudaGetSymbolAddress((void**)&projT, h_projT);
    cudaGetSymbolAddress((void**)&fc1T,  h_fc1T);
    cudaGetSymbolAddress((void**)&fc2T,  h_fc2T);
    cudaGetSymbolAddress((void**)&vT,    h_vT);

    transpose_h_kernel<<<dim3(3*DIM/32, DIM/32), 256>>>(qkv_w, qkvT, DIM, 3*DIM);
    transpose_h_kernel<<<dim3(DIM/32, DIM/32), 256>>>(proj_w, projT, DIM, DIM);
    transpose_h_kernel<<<dim3(MLP/32, DIM/32), 256>>>(fc1_w, fc1T, DIM, MLP);
    transpose_h_kernel<<<dim3(DIM/32, MLP/32), 256>>>(fc2_w, fc2T, MLP, DIM);

    ln_kernel<<<TT, 256>>>(x, ln1_w, ln1_b, xn);
    gemm_h<0><<<dim3(3*DIM/128, TT/128), 128>>>(TT, 3*DIM, DIM, xn, qkvT, qkv_b, nullptr, qkv);
    vt_kernel<<<dim3(SS/32, HDIM/32, BB*HEADS), 256>>>(qkv, vT);
    attn_mma<<<dim3(SS/64, BB*HEADS), 128>>>(qkv, vT, attn);
    gemm_h<2><<<dim3(DIM/128, TT/128), 128>>>(TT, DIM, DIM, attn, projT, proj_b, x, x1);
    ln_kernel<<<TT, 256>>>(x1, ln2_w, ln2_b, xn);
    gemm_h<1><<<dim3(MLP/128, TT/128), 128>>>(TT, MLP, DIM, xn, fc1T, fc1_b, nullptr, hh);
    gemm_h<2><<<dim3(DIM/128, TT/128), 128>>>(TT, DIM, MLP, hh, fc2T, fc2_b, x1, out);
}

// round 7
// speedup vs baseline: 9.9119x; 1.0038x over previous
#include <cuda_runtime.h>
#include <cuda_fp16.h>
#include <math.h>
#include <stdint.h>

#define DIM   1024
#define HEADS 16
#define HDIM  64
#define MLP   4096
#define BB    4
#define SS    2048
#define TT    (BB*SS)   // 8192 tokens

// ---------------- scratch (device globals; no allocation) ----------------
__device__ __half h_xn[(size_t)TT*DIM];
__device__ __half h_qkv[(size_t)TT*3*DIM];
__device__ __half h_attn[(size_t)TT*DIM];
__device__ float  g_x1[(size_t)TT*DIM];
__device__ __half h_h[(size_t)TT*MLP];
__device__ __half h_qkvT[(size_t)3*DIM*DIM];
__device__ __half h_projT[(size_t)DIM*DIM];
__device__ __half h_fc1T[(size_t)DIM*MLP];
__device__ __half h_fc2T[(size_t)MLP*DIM];

// ---------------- ptx helpers ----------------
__device__ __forceinline__ void mma_f16(float* c, const uint32_t* a, const uint32_t* b) {
    asm volatile(
        "mma.sync.aligned.m16n8k16.row.col.f32.f16.f16.f32 "
        "{%0,%1,%2,%3}, {%4,%5,%6,%7}, {%8,%9}, {%0,%1,%2,%3};"
        : "+f"(c[0]), "+f"(c[1]), "+f"(c[2]), "+f"(c[3])
        : "r"(a[0]), "r"(a[1]), "r"(a[2]), "r"(a[3]), "r"(b[0]), "r"(b[1]));
}

__device__ __forceinline__ void ldmx4(uint32_t& r0, uint32_t& r1, uint32_t& r2, uint32_t& r3,
                                      const __half* p) {
    uint32_t a = (uint32_t)__cvta_generic_to_shared((void*)p);
    asm volatile("ldmatrix.sync.aligned.m8n8.x4.shared.b16 {%0,%1,%2,%3}, [%4];"
                 : "=r"(r0), "=r"(r1), "=r"(r2), "=r"(r3) : "r"(a));
}

__device__ __forceinline__ void ldmx4t(uint32_t& r0, uint32_t& r1, uint32_t& r2, uint32_t& r3,
                                       const __half* p) {
    uint32_t a = (uint32_t)__cvta_generic_to_shared((void*)p);
    asm volatile("ldmatrix.sync.aligned.m8n8.x4.trans.shared.b16 {%0,%1,%2,%3}, [%4];"
                 : "=r"(r0), "=r"(r1), "=r"(r2), "=r"(r3) : "r"(a));
}

__device__ __forceinline__ void cpa16(__half* dst, const __half* src) {
    uint32_t s = (uint32_t)__cvta_generic_to_shared((void*)dst);
    asm volatile("cp.async.cg.shared.global [%0], [%1], 16;" :: "r"(s), "l"(src));
}
#define CP_COMMIT() asm volatile("cp.async.commit_group;" ::: "memory")
#define CP_WAIT2()  asm volatile("cp.async.wait_group 2;" ::: "memory")
#define CP_WAIT1()  asm volatile("cp.async.wait_group 1;" ::: "memory")

// ---------------- LayerNorm: fp32 in -> fp16 out ----------------
__global__ __launch_bounds__(256)
void ln_kernel(const float* __restrict__ x, const float* __restrict__ w,
               const float* __restrict__ b, __half* __restrict__ out) {
    int row = blockIdx.x;
    int tid = threadIdx.x;
    const float4* xr = (const float4*)(x + (size_t)row * DIM);
    float4 v = xr[tid];
    float s  = v.x + v.y + v.z + v.w;
    float ss = v.x*v.x + v.y*v.y + v.z*v.z + v.w*v.w;
    #pragma unroll
    for (int o = 16; o; o >>= 1) {
        s  += __shfl_xor_sync(0xffffffffu, s,  o);
        ss += __shfl_xor_sync(0xffffffffu, ss, o);
    }
    __shared__ float red0[8], red1[8];
    int wid = tid >> 5, lid = tid & 31;
    if (lid == 0) { red0[wid] = s; red1[wid] = ss; }
    __syncthreads();
    float sum = 0.f, sumsq = 0.f;
    #pragma unroll
    for (int i = 0; i < 8; i++) { sum += red0[i]; sumsq += red1[i]; }
    float mu   = sum * (1.0f / DIM);
    float var  = sumsq * (1.0f / DIM) - mu * mu;
    float rstd = rsqrtf(var + 1e-5f);
    float4 wv = ((const float4*)w)[tid];
    float4 bv = ((const float4*)b)[tid];
    __half2* o2 = (__half2*)(out + (size_t)row * DIM);
    o2[tid*2+0] = __floats2half2_rn((v.x - mu)*rstd*wv.x + bv.x,
                                    (v.y - mu)*rstd*wv.y + bv.y);
    o2[tid*2+1] = __floats2half2_rn((v.z - mu)*rstd*wv.z + bv.z,
                                    (v.w - mu)*rstd*wv.w + bv.w);
}

// ---------------- weight transpose [K,N] fp32 -> [N,K] fp16 ----------------
__global__ __launch_bounds__(256)
void transpose_h_kernel(const float* __restrict__ in, __half* __restrict__ out,
                        int K, int N) {
    __shared__ float tile[32][33];
    int bx = blockIdx.x;
    int by = blockIdx.y;
    int tx = threadIdx.x & 31;
    int ty = threadIdx.x >> 5;
    #pragma unroll
    for (int i = 0; i < 32; i += 8)
        tile[ty + i][tx] = in[(size_t)(by * 32 + ty + i) * N + bx * 32 + tx];
    __syncthreads();
    #pragma unroll
    for (int i = 0; i < 32; i += 8)
        out[(size_t)(bx * 32 + ty + i) * K + by * 32 + tx] = __float2half_rn(tile[tx][ty + i]);
}

// ---------------- fp16 mma GEMM, 4-stage cp.async + ldmatrix, 1 sync/chunk ----------------
#define GLDA 40
#define STG_H (2 * 128 * GLDA)

template <int EPI>
__global__ __launch_bounds__(128, 2)
void gemm_h(int M, int N, int K,
            const __half* __restrict__ A, const __half* __restrict__ Bt,
            const float* __restrict__ bias, const float* __restrict__ R,
            void* __restrict__ Cout) {
    __shared__ __half sh[4 * STG_H];

    int tid = threadIdx.x;
    int wid = tid >> 5, lane = tid & 31;
    int gid = lane >> 2, tg = lane & 3;
    int wm = wid & 1, wn = wid >> 1;
    int bx = blockIdx.x, by = blockIdx.y;

    const __half* Ab = A  + (size_t)(by * 128) * K;
    const __half* Bb = Bt + (size_t)(bx * 128) * K;

    float acc[4][8][4];
    #pragma unroll
    for (int i = 0; i < 4; i++)
        #pragma unroll
        for (int j = 0; j < 8; j++)
            #pragma unroll
            for (int c = 0; c < 4; c++) acc[i][j][c] = 0.f;

    int NC = K / 32;

    auto issue = [&](int s) {
        if (s < NC) {
            __half* sa = sh + (s & 3) * STG_H;
            __half* sb = sa + 128 * GLDA;
            int kb = s * 32;
            #pragma unroll
            for (int it = 0; it < 4; it++) {
                int idx = it * 128 + tid;
                int r = idx >> 2, c8 = (idx & 3) * 8;
                cpa16(sa + r * GLDA + c8, Ab + (size_t)r * K + kb + c8);
                cpa16(sb + r * GLDA + c8, Bb + (size_t)r * K + kb + c8);
            }
        }
        CP_COMMIT();
    };

    issue(0); issue(1); issue(2);

    for (int kc = 0; kc < NC; kc++) {
        CP_WAIT2();
        __syncthreads();
        issue(kc + 3);

        const __half* Ac = sh + (kc & 3) * STG_H;
        const __half* Bc = Ac + 128 * GLDA;

        #pragma unroll
        for (int kk = 0; kk < 32; kk += 16) {
            uint32_t af[4][4];
            #pragma unroll
            for (int mf = 0; mf < 4; mf++) {
                const __half* p = Ac + (wm * 64 + mf * 16 + (lane & 15)) * GLDA
                                  + kk + (lane >> 4) * 8;
                ldmx4(af[mf][0], af[mf][1], af[mf][2], af[mf][3], p);
            }
            uint32_t bf[8][2];
            #pragma unroll
            for (int pj = 0; pj < 4; pj++) {
                const __half* p = Bc + (wn * 64 + (pj * 2 + (lane >> 4)) * 8 + (lane & 7)) * GLDA
                                  + kk + ((lane >> 3) & 1) * 8;
                ldmx4(bf[2*pj][0], bf[2*pj][1], bf[2*pj+1][0], bf[2*pj+1][1], p);
            }
            #pragma unroll
            for (int mf = 0; mf < 4; mf++)
                #pragma unroll
                for (int nb = 0; nb < 8; nb++)
                    mma_f16(acc[mf][nb], af[mf], bf[nb]);
        }
    }

    // epilogue
    int colW = bx * 128 + wn * 64;
    #pragma unroll
    for (int mf = 0; mf < 4; mf++) {
        #pragma unroll
        for (int r2 = 0; r2 < 2; r2++) {
            int row = by * 128 + wm * 64 + mf * 16 + gid + r2 * 8;
            #pragma unroll
            for (int nb = 0; nb < 8; nb++) {
                int gcol = colW + nb * 8 + 2 * tg;
                float t0 = acc[mf][nb][r2 * 2 + 0] + bias[gcol];
                float t1 = acc[mf][nb][r2 * 2 + 1] + bias[gcol + 1];
                if (EPI == 1) {
                    t0 = 0.5f * t0 * (1.0f + erff(t0 * 0.70710678118654752f));
                    t1 = 0.5f * t1 * (1.0f + erff(t1 * 0.70710678118654752f));
                }
                if (EPI == 2) {
                    float2 rv = *(const float2*)(R + (size_t)row * N + gcol);
                    t0 += rv.x; t1 += rv.y;
                    *(float2*)((float*)Cout + (size_t)row * N + gcol) = make_float2(t0, t1);
                } else {
                    *(__half2*)((__half*)Cout + (size_t)row * N + gcol) = __floats2half2_rn(t0, t1);
                }
            }
        }
    }
}

// ---------------- causal flash attention: 128 q/CTA, 8 warps, V via ldmatrix.trans ----------------
#define KLD 72
#define ATILE (64 * KLD)

__global__ __launch_bounds__(256)
void attn_mma(const __half* __restrict__ qkv, __half* __restrict__ out) {
    int qt = blockIdx.x, bh = blockIdx.y;     // qt: 0..15 (128-query tiles)
    int b = bh >> 4, h = bh & 15;
    int tid = threadIdx.x;
    int wid = tid >> 5, lane = tid & 31;
    int gid = lane >> 2, tg = lane & 3;
    int q0 = qt * 128;
    int ntiles = 2 * qt + 2;

    __shared__ __half Ks3[3 * ATILE];   // [key][dim]
    __shared__ __half Vs3[3 * ATILE];   // [key][dim]

    auto issueA = [&](int s) {
        if (s < ntiles) {
            __half* ka = Ks3 + (s % 3) * ATILE;
            __half* va = Vs3 + (s % 3) * ATILE;
            #pragma unroll
            for (int it = 0; it < 2; it++) {
                int idx = it * 256 + tid;
                int r = idx >> 3, c8 = (idx & 7) * 8;
                const __half* src = qkv + ((size_t)(b * SS) + s * 64 + r) * (3 * DIM) + h * HDIM + c8;
                cpa16(ka + r * KLD + c8, src + DIM);
                cpa16(va + r * KLD + c8, src + 2 * DIM);
            }
        }
        CP_COMMIT();
    };

    uint32_t qa[4][4];
    {
        const __half* Q0 = qkv + ((size_t)(b * SS) + q0 + wid * 16 + gid) * (3 * DIM) + h * HDIM + 2 * tg;
        const __half* Q1 = Q0 + (size_t)8 * (3 * DIM);
        #pragma unroll
        for (int kcc = 0; kcc < 4; kcc++) {
            qa[kcc][0] = *(const uint32_t*)(Q0 + kcc * 16);
            qa[kcc][1] = *(const uint32_t*)(Q1 + kcc * 16);
            qa[kcc][2] = *(const uint32_t*)(Q0 + kcc * 16 + 8);
            qa[kcc][3] = *(const uint32_t*)(Q1 + kcc * 16 + 8);
        }
    }

    issueA(0); issueA(1);

    float oacc[8][4];
    #pragma unroll
    for (int nb = 0; nb < 8; nb++)
        #pragma unroll
        for (int c = 0; c < 4; c++) oacc[nb][c] = 0.f;
    float m0 = -1e30f, m1 = -1e30f, l0 = 0.f, l1 = 0.f;
    int rg0 = q0 + wid * 16 + gid;
    int rg1 = rg0 + 8;

    int lm_row = ((lane >> 4)) * 8 + (lane & 7);
    int lm_koff = ((lane >> 3) & 1) * 8;
    // trans (V) addressing: row = key, col-halves = d
    int vt_row = (lane & 7) + ((lane >> 3) & 1) * 8;
    int vt_col = (lane >> 4) * 8;

    for (int jt = 0; jt < ntiles; jt++) {
        CP_WAIT1();
        __syncthreads();
        issueA(jt + 2);

        const __half* Kc = Ks3 + (jt % 3) * ATILE;
        const __half* Vc = Vs3 + (jt % 3) * ATILE;

        // S = Q @ K^T
        float sacc[8][4];
        #pragma unroll
        for (int nb = 0; nb < 8; nb++)
            #pragma unroll
            for (int c = 0; c < 4; c++) sacc[nb][c] = 0.f;
        #pragma unroll
        for (int kcc = 0; kcc < 4; kcc++) {
            uint32_t bf[8][2];
            #pragma unroll
            for (int pj = 0; pj < 4; pj++) {
                const __half* p = Kc + (pj * 16 + lm_row) * KLD + kcc * 16 + lm_koff;
                ldmx4(bf[2*pj][0], bf[2*pj][1], bf[2*pj+1][0], bf[2*pj+1][1], p);
            }
            #pragma unroll
            for (int nb = 0; nb < 8; nb++)
                mma_f16(sacc[nb], qa[kcc], bf[nb]);
        }

        const float sc = 0.125f;
        float tm0 = -1e30f, tm1 = -1e30f;
        bool need_mask = (jt >= 2 * qt);
        #pragma unroll
        for (int nb = 0; nb < 8; nb++) {
            int col = jt * 64 + nb * 8 + 2 * tg;
            float s0 = sacc[nb][0] * sc, s1 = sacc[nb][1] * sc;
            float s2 = sacc[nb][2] * sc, s3 = sacc[nb][3] * sc;
            if (need_mask) {
                if (col     > rg0) s0 = -1e30f;
                if (col + 1 > rg0) s1 = -1e30f;
                if (col     > rg1) s2 = -1e30f;
                if (col + 1 > rg1) s3 = -1e30f;
            }
            sacc[nb][0] = s0; sacc[nb][1] = s1; sacc[nb][2] = s2; sacc[nb][3] = s3;
            tm0 = fmaxf(tm0, fmaxf(s0, s1));
            tm1 = fmaxf(tm1, fmaxf(s2, s3));
        }
        tm0 = fmaxf(tm0, __shfl_xor_sync(0xffffffffu, tm0, 1));
        tm0 = fmaxf(tm0, __shfl_xor_sync(0xffffffffu, tm0, 2));
        tm1 = fmaxf(tm1, __shfl_xor_sync(0xffffffffu, tm1, 1));
        tm1 = fmaxf(tm1, __shfl_xor_sync(0xffffffffu, tm1, 2));

        float mn0 = fmaxf(m0, tm0), mn1 = fmaxf(m1, tm1);
        float cr0 = __expf(m0 - mn0), cr1 = __expf(m1 - mn1);
        l0 *= cr0; l1 *= cr1;
        #pragma unroll
        for (int nb = 0; nb < 8; nb++) {
            oacc[nb][0] *= cr0; oacc[nb][1] *= cr0;
            oacc[nb][2] *= cr1; oacc[nb][3] *= cr1;
        }
        uint32_t pa01[8], pa23[8];
        #pragma unroll
        for (int nb = 0; nb < 8; nb++) {
            float p0 = __expf(sacc[nb][0] - mn0);
            float p1 = __expf(sacc[nb][1] - mn0);
            float p2 = __expf(sacc[nb][2] - mn1);
            float p3 = __expf(sacc[nb][3] - mn1);
            l0 += p0 + p1; l1 += p2 + p3;
            __half2 h01 = __floats2half2_rn(p0, p1);
            __half2 h23 = __floats2half2_rn(p2, p3);
            pa01[nb] = *(uint32_t*)&h01;
            pa23[nb] = *(uint32_t*)&h23;
        }
        m0 = mn0; m1 = mn1;

        // O += P @ V  (B-fragments via ldmatrix.trans from [key][dim] tile)
        #pragma unroll
        for (int kcc = 0; kcc < 4; kcc++) {
            uint32_t aa[4] = { pa01[2*kcc], pa23[2*kcc], pa01[2*kcc+1], pa23[2*kcc+1] };
            uint32_t bf[8][2];
            #pragma unroll
            for (int pj = 0; pj < 4; pj++) {
                const __half* p = Vc + (kcc * 16 + vt_row) * KLD + pj * 16 + vt_col;
                ldmx4t(bf[2*pj][0], bf[2*pj][1], bf[2*pj+1][0], bf[2*pj+1][1], p);
            }
            #pragma unroll
            for (int nb = 0; nb < 8; nb++)
                mma_f16(oacc[nb], aa, bf[nb]);
        }
    }

    l0 += __shfl_xor_sync(0xffffffffu, l0, 1);
    l0 += __shfl_xor_sync(0xffffffffu, l0, 2);
    l1 += __shfl_xor_sync(0xffffffffu, l1, 1);
    l1 += __shfl_xor_sync(0xffffffffu, l1, 2);
    float i0 = 1.0f / l0, i1 = 1.0f / l1;

    __half* o0 = out + ((size_t)(b * SS) + rg0) * DIM + h * HDIM + 2 * tg;
    __half* o1 = out + ((size_t)(b * SS) + rg1) * DIM + h * HDIM + 2 * tg;
    #pragma unroll
    for (int nb = 0; nb < 8; nb++) {
        *(__half2*)(o0 + nb * 8) = __floats2half2_rn(oacc[nb][0] * i0, oacc[nb][1] * i0);
        *(__half2*)(o1 + nb * 8) = __floats2half2_rn(oacc[nb][2] * i1, oacc[nb][3] * i1);
    }
}

// ---------------- launch ----------------
extern "C" void kernel_launch(void* const* d_in, const int* in_sizes, int n_in,
                              void* d_out, int out_size) {
    const float* x      = (const float*)d_in[0];
    const float* ln1_w  = (const float*)d_in[1];
    const float* ln1_b  = (const float*)d_in[2];
    const float* qkv_w  = (const float*)d_in[3];
    const float* qkv_b  = (const float*)d_in[4];
    const float* proj_w = (const float*)d_in[5];
    const float* proj_b = (const float*)d_in[6];
    const float* ln2_w  = (const float*)d_in[7];
    const float* ln2_b  = (const float*)d_in[8];
    const float* fc1_w  = (const float*)d_in[9];
    const float* fc1_b  = (const float*)d_in[10];
    const float* fc2_w  = (const float*)d_in[11];
    const float* fc2_b  = (const float*)d_in[12];
    float* out = (float*)d_out;

    __half *xn, *qkv, *attn, *hh, *qkvT, *projT, *fc1T, *fc2T;
    float *x1;
    cudaGetSymbolAddress((void**)&xn,    h_xn);
    cudaGetSymbolAddress((void**)&qkv,   h_qkv);
    cudaGetSymbolAddress((void**)&attn,  h_attn);
    cudaGetSymbolAddress((void**)&x1,    g_x1);
    cudaGetSymbolAddress((void**)&hh,    h_h);
    cudaGetSymbolAddress((void**)&qkvT,  h_qkvT);
    cudaGetSymbolAddress((void**)&projT, h_projT);
    cudaGetSymbolAddress((void**)&fc1T,  h_fc1T);
    cudaGetSymbolAddress((void**)&fc2T,  h_fc2T);

    static cudaStream_t s_tr = nullptr;
    static cudaEvent_t ev_fork = nullptr, ev_qkvT = nullptr, ev_wT = nullptr;
    if (!s_tr) {
        cudaStreamCreateWithFlags(&s_tr, cudaStreamNonBlocking);
        cudaEventCreateWithFlags(&ev_fork, cudaEventDisableTiming);
        cudaEventCreateWithFlags(&ev_qkvT, cudaEventDisableTiming);
        cudaEventCreateWithFlags(&ev_wT,   cudaEventDisableTiming);
    }

    // fork: weight transposes on side stream
    cudaEventRecord(ev_fork, 0);
    cudaStreamWaitEvent(s_tr, ev_fork, 0);
    transpose_h_kernel<<<dim3(3*DIM/32, DIM/32), 256, 0, s_tr>>>(qkv_w, qkvT, DIM, 3*DIM);
    cudaEventRecord(ev_qkvT, s_tr);
    transpose_h_kernel<<<dim3(DIM/32, DIM/32), 256, 0, s_tr>>>(proj_w, projT, DIM, DIM);
    transpose_h_kernel<<<dim3(MLP/32, DIM/32), 256, 0, s_tr>>>(fc1_w, fc1T, DIM, MLP);
    transpose_h_kernel<<<dim3(DIM/32, MLP/32), 256, 0, s_tr>>>(fc2_w, fc2T, MLP, DIM);
    cudaEventRecord(ev_wT, s_tr);

    // main stream
    ln_kernel<<<TT, 256>>>(x, ln1_w, ln1_b, xn);
    cudaStreamWaitEvent(0, ev_qkvT, 0);
    gemm_h<0><<<dim3(3*DIM/128, TT/128), 128>>>(TT, 3*DIM, DIM, xn, qkvT, qkv_b, nullptr, qkv);
    attn_mma<<<dim3(SS/128, BB*HEADS), 256>>>(qkv, attn);
    cudaStreamWaitEvent(0, ev_wT, 0);
    gemm_h<2><<<dim3(DIM/128, TT/128), 128>>>(TT, DIM, DIM, attn, projT, proj_b, x, x1);
    ln_kernel<<<TT, 256>>>(x1, ln2_w, ln2_b, xn);
    gemm_h<1><<<dim3(MLP/128, TT/128), 128>>>(TT, MLP, DIM, xn, fc1T, fc1_b, nullptr, hh);
    gemm_h<2><<<dim3(DIM/128, TT/128), 128>>>(TT, DIM, MLP, hh, fc2T, fc2_b, x1, out);
}